// round 5
// baseline (speedup 1.0000x reference)
#include <cuda_runtime.h>
#include <math.h>
#include <stdint.h>

// B=2, S=2048, T=4096, D_IN=2048, H=16, QK_HEAD=128 (64 nope + 64 rope),
// V_HEAD=128, KV_RANK=512, D_OUT=2048
#define TOKS 4096
#define SEQ  2048

// ---------------------------------------------------------------------------
// Scratch
// ---------------------------------------------------------------------------
__device__ float g_q[(size_t)TOKS * 2048];
__device__ float g_kv[(size_t)TOKS * 576];
__device__ float g_kvc[(size_t)TOKS * 512];
__device__ float g_kpe[(size_t)TOKS * 64];
__device__ float g_kvdec[(size_t)TOKS * 3072];
__device__ float g_attn[(size_t)TOKS * 2048];

// ---------------------------------------------------------------------------
// Helpers
// ---------------------------------------------------------------------------
__device__ __forceinline__ uint32_t f2tf(float x) {
    uint32_t u;
    asm("cvt.rna.tf32.f32 %0, %1;" : "=r"(u) : "f"(x));
    return u;
}

__device__ __forceinline__ void mma_tf32(float* d, const uint32_t* a, const uint32_t* b) {
    asm volatile(
        "mma.sync.aligned.m16n8k8.row.col.f32.tf32.tf32.f32 "
        "{%0,%1,%2,%3}, {%4,%5,%6,%7}, {%8,%9}, {%0,%1,%2,%3};\n"
        : "+f"(d[0]), "+f"(d[1]), "+f"(d[2]), "+f"(d[3])
        : "r"(a[0]), "r"(a[1]), "r"(a[2]), "r"(a[3]), "r"(b[0]), "r"(b[1]));
}

// ---------------------------------------------------------------------------
// TF32 GEMM v2: C[M,N] = A[M,K] @ B[K,N], fp32 in/out.
// BM=128, BN=128, BK=32, 256 thr / 8 warps, warp tile 64x32.
// A staged as TF32 with permuted cols: word j of row r = A[r][4j + tig-part];
//   fragment loads become LDS.128 (2 per row per 32-k chunk, 4 ks each).
// B staged as TF32 [k][n], stride 136 (LDS.32 frags, conflict-free).
// Reg-prefetch double buffering (no cp.async; cvt happens once at staging).
// ---------------------------------------------------------------------------
#define G_ASTR 36
#define G_BSTR 136
#define G_AW  (128 * G_ASTR)   // 4608 words
#define G_BW  (32 * G_BSTR)    // 4352 words
#define GEMM_SMEM ((2 * G_AW + 2 * G_BW) * 4)

__global__ __launch_bounds__(256)
void gemm_tf32(const float* __restrict__ A, const float* __restrict__ B,
               float* __restrict__ C, int M, int N, int K)
{
    extern __shared__ uint32_t smw[];
    uint32_t* AqB[2] = { smw, smw + G_AW };
    uint32_t* BqB[2] = { smw + 2 * G_AW, smw + 2 * G_AW + G_BW };

    const int t = threadIdx.x;
    const int lane = t & 31;
    const int wid = t >> 5;
    const int g = lane >> 2, tig = lane & 3;
    const int wm = wid >> 2;      // 0..1 -> 64 rows
    const int wn = wid & 3;       // 0..3 -> 32 cols
    const int row0 = blockIdx.y * 128;
    const int col0 = blockIdx.x * 128;

    float acc[4][4][4];
#pragma unroll
    for (int mt = 0; mt < 4; mt++)
#pragma unroll
        for (int nt = 0; nt < 4; nt++)
#pragma unroll
            for (int i = 0; i < 4; i++) acc[mt][nt][i] = 0.f;

    float4 apre[4], bpre[4];
    const int nkt = K >> 5;

    // ---- prefetch helpers (inlined manually) ----
    // A ids: r = id>>3 (0..127), kc = (id&7)*4 ; B ids: br = id>>5, bnc = (id&31)*4
#define G_LDG(k0)                                                              \
    {                                                                          \
        _Pragma("unroll")                                                      \
        for (int i = 0; i < 4; i++) {                                          \
            const int id = t + i * 256;                                        \
            const int ar = id >> 3, akc = (id & 7) * 4;                        \
            apre[i] = *(const float4*)(A + (size_t)(row0 + ar) * K + (k0) + akc); \
            const int br = id >> 5, bnc = (id & 31) * 4;                       \
            const int col = col0 + bnc;                                        \
            bpre[i] = (col < N)                                                \
                ? *(const float4*)(B + (size_t)((k0) + br) * N + col)          \
                : make_float4(0.f, 0.f, 0.f, 0.f);                             \
        }                                                                      \
    }
#define G_STS(buf)                                                             \
    {                                                                          \
        uint32_t* Aq = AqB[buf];                                               \
        uint32_t* Bq = BqB[buf];                                               \
        _Pragma("unroll")                                                      \
        for (int i = 0; i < 4; i++) {                                          \
            const int id = t + i * 256;                                        \
            const int ar = id >> 3, akc = (id & 7) * 4;                        \
            const int ab = ar * G_ASTR + (akc >> 2);                           \
            Aq[ab + 0]  = f2tf(apre[i].x);                                     \
            Aq[ab + 8]  = f2tf(apre[i].y);                                     \
            Aq[ab + 16] = f2tf(apre[i].z);                                     \
            Aq[ab + 24] = f2tf(apre[i].w);                                     \
            const int br = id >> 5, bnc = (id & 31) * 4;                       \
            *(uint4*)(Bq + br * G_BSTR + bnc) =                                \
                make_uint4(f2tf(bpre[i].x), f2tf(bpre[i].y),                   \
                           f2tf(bpre[i].z), f2tf(bpre[i].w));                  \
        }                                                                      \
    }

    G_LDG(0);
    G_STS(0);
    __syncthreads();

    for (int kt = 0; kt < nkt; kt++) {
        if (kt + 1 < nkt) G_LDG((kt + 1) << 5);

        const uint32_t* Aq = AqB[kt & 1];
        const uint32_t* Bq = BqB[kt & 1];

        // B fragments for all 4 ks
        uint32_t bfr[4][4][2];
#pragma unroll
        for (int ks = 0; ks < 4; ks++)
#pragma unroll
            for (int nt = 0; nt < 4; nt++) {
                const uint32_t* bp = Bq + (ks * 8 + tig) * G_BSTR + wn * 32 + nt * 8 + g;
                bfr[ks][nt][0] = bp[0];
                bfr[ks][nt][1] = bp[4 * G_BSTR];
            }
#pragma unroll
        for (int mt = 0; mt < 4; mt++) {
            const int ra = (wm * 64 + mt * 16 + g) * G_ASTR + tig * 8;
            const uint4 qg0 = *(const uint4*)(Aq + ra);
            const uint4 qg1 = *(const uint4*)(Aq + ra + 4);
            const uint4 qh0 = *(const uint4*)(Aq + ra + 8 * G_ASTR);
            const uint4 qh1 = *(const uint4*)(Aq + ra + 8 * G_ASTR + 4);
            const uint32_t a0[4] = {qg0.x, qh0.x, qg0.y, qh0.y};
            const uint32_t a1[4] = {qg0.z, qh0.z, qg0.w, qh0.w};
            const uint32_t a2[4] = {qg1.x, qh1.x, qg1.y, qh1.y};
            const uint32_t a3[4] = {qg1.z, qh1.z, qg1.w, qh1.w};
#pragma unroll
            for (int nt = 0; nt < 4; nt++) {
                mma_tf32(acc[mt][nt], a0, bfr[0][nt]);
                mma_tf32(acc[mt][nt], a1, bfr[1][nt]);
                mma_tf32(acc[mt][nt], a2, bfr[2][nt]);
                mma_tf32(acc[mt][nt], a3, bfr[3][nt]);
            }
        }

        if (kt + 1 < nkt) G_STS((kt + 1) & 1);
        __syncthreads();
    }

#pragma unroll
    for (int mt = 0; mt < 4; mt++) {
        const int gr0 = row0 + wm * 64 + mt * 16 + g;
#pragma unroll
        for (int nt = 0; nt < 4; nt++) {
            const int gc = col0 + wn * 32 + nt * 8 + 2 * tig;
            if (gc < N) {
                *(float2*)(C + (size_t)gr0 * N + gc) =
                    make_float2(acc[mt][nt][0], acc[mt][nt][1]);
                *(float2*)(C + (size_t)(gr0 + 8) * N + gc) =
                    make_float2(acc[mt][nt][2], acc[mt][nt][3]);
            }
        }
    }
}

// ---------------------------------------------------------------------------
// RMSNorm over 512 latent dims
// ---------------------------------------------------------------------------
__global__ __launch_bounds__(128)
void rmsnorm_kernel(const float* __restrict__ kv, const float* __restrict__ w,
                    float* __restrict__ out)
{
    __shared__ float red[4];
    const int tok = blockIdx.x;
    const int t = threadIdx.x;
    const float* row = kv + (size_t)tok * 576;
    float v[4];
    float s = 0.0f;
#pragma unroll
    for (int u = 0; u < 4; u++) {
        v[u] = row[t + u * 128];
        s = fmaf(v[u], v[u], s);
    }
#pragma unroll
    for (int off = 16; off > 0; off >>= 1)
        s += __shfl_down_sync(0xffffffffu, s, off);
    if ((t & 31) == 0) red[t >> 5] = s;
    __syncthreads();
    const float tot = red[0] + red[1] + red[2] + red[3];
    const float r = rsqrtf(tot * (1.0f / 512.0f) + 1e-6f);
    float* orow = out + (size_t)tok * 512;
#pragma unroll
    for (int u = 0; u < 4; u++) {
        const int idx = t + u * 128;
        orow[idx] = v[u] * r * w[idx];
    }
}

// ---------------------------------------------------------------------------
// RoPE
// ---------------------------------------------------------------------------
__global__ __launch_bounds__(512)
void rope_q_kernel(float* __restrict__ q)
{
    const int tok = blockIdx.x;
    const int h = threadIdx.x >> 5;
    const int i = threadIdx.x & 31;
    const int s = tok & (SEQ - 1);
    const float e = (float)(2 * i) * (1.0f / 64.0f);
    const float freq = 1.0f / powf(10000.0f, e);
    float sn, c;
    sincosf((float)s * freq, &sn, &c);
    float* base = q + ((size_t)tok * 16 + h) * 128 + 64;
    const float x1 = base[2 * i];
    const float x2 = base[2 * i + 1];
    base[2 * i]     = x1 * c - x2 * sn;
    base[2 * i + 1] = x2 * c + x1 * sn;
}

__global__ __launch_bounds__(32)
void rope_k_kernel(const float* __restrict__ kv, float* __restrict__ kpe)
{
    const int tok = blockIdx.x;
    const int i = threadIdx.x;
    const int s = tok & (SEQ - 1);
    const float e = (float)(2 * i) * (1.0f / 64.0f);
    const float freq = 1.0f / powf(10000.0f, e);
    float sn, c;
    sincosf((float)s * freq, &sn, &c);
    const float* src = kv + (size_t)tok * 576 + 512;
    const float x1 = src[2 * i];
    const float x2 = src[2 * i + 1];
    kpe[(size_t)tok * 64 + 2 * i]     = x1 * c - x2 * sn;
    kpe[(size_t)tok * 64 + 2 * i + 1] = x2 * c + x1 * sn;
}

// ---------------------------------------------------------------------------
// Flash attention v2 (causal, TF32 mma). 128q x 64k tiles, d=128, 8 warps.
// Q/K staged pre-converted TF32 with permuted cols (LDS.128 fragments).
// V staged pre-converted TF32 [key][d].
// P: raw fp32 scores -> softmax (2 threads/row) -> in-place permuted TF32.
// ---------------------------------------------------------------------------
#define FQ 128
#define FKEY 64
#define QSTRW 132
#define KSTRW 132
#define VSTRW 136
#define PSTRW 68
#define SM_KP (FQ * QSTRW)
#define SM_VQ (SM_KP + FKEY * KSTRW)
#define SM_P  (SM_VQ + FKEY * VSTRW)
#define SM_RM (SM_P + FQ * PSTRW)
#define FLASH_SMEM ((SM_RM + 3 * FQ) * 4)

__global__ __launch_bounds__(256)
void flash_mma2(const float* __restrict__ q, const float* __restrict__ kvdec,
                const float* __restrict__ kpe, float* __restrict__ o)
{
    extern __shared__ uint32_t smw[];
    uint32_t* Qp = smw;
    uint32_t* Kp = smw + SM_KP;
    uint32_t* Vq = smw + SM_VQ;
    float*    Pf = (float*)(smw + SM_P);
    uint32_t* Pu = smw + SM_P;
    float* rm = (float*)(smw + SM_RM);
    float* rl = rm + FQ;
    float* rf = rl + FQ;

    const int t = threadIdx.x;
    const int lane = t & 31, wid = t >> 5;
    const int g = lane >> 2, tig = lane & 3;
    const int wm = wid >> 1;   // 0..3: 32-row band
    const int wn = wid & 1;    // 0..1
    const int qb = blockIdx.x, h = blockIdx.y, b = blockIdx.z;
    const int q0 = qb * FQ;
    const float scale = 0.08838834764831845f;  // 1/sqrt(128)

    // stage Q: pre-scale, cvt, permuted store
#pragma unroll
    for (int i = 0; i < 16; i++) {
        const int id = t + i * 256;
        const int r = id >> 5, dc = (id & 31) * 4;
        float4 v = *(const float4*)(q + (((size_t)(b * SEQ + q0 + r) * 16 + h) << 7) + dc);
        const int base = r * QSTRW + (dc & 96) + ((dc & 31) >> 2);
        Qp[base + 0]  = f2tf(v.x * scale);
        Qp[base + 8]  = f2tf(v.y * scale);
        Qp[base + 16] = f2tf(v.z * scale);
        Qp[base + 24] = f2tf(v.w * scale);
    }
    if (t < FQ) { rm[t] = -1e30f; rl[t] = 0.f; }

    float oacc[2][8][4];
#pragma unroll
    for (int mt = 0; mt < 2; mt++)
#pragma unroll
        for (int nt = 0; nt < 8; nt++)
#pragma unroll
            for (int i = 0; i < 4; i++) oacc[mt][nt][i] = 0.f;

    const int nkt = 2 * (qb + 1);
    for (int kt = 0; kt < nkt; kt++) {
        __syncthreads();
        const int k0 = kt * FKEY;
        // stage K (nope|rope, permuted) and V (plain, converted)
#pragma unroll
        for (int i = 0; i < 8; i++) {
            const int id = t + i * 256;
            const int r = id >> 5, dc = (id & 31) * 4;
            const size_t tok = (size_t)(b * SEQ + k0 + r);
            const float* kvrow = kvdec + (tok * 16 + h) * 192;
            float4 kv4 = (dc < 64) ? *(const float4*)(kvrow + dc)
                                   : *(const float4*)(kpe + tok * 64 + (dc - 64));
            const int kb = r * KSTRW + (dc & 96) + ((dc & 31) >> 2);
            Kp[kb + 0]  = f2tf(kv4.x);
            Kp[kb + 8]  = f2tf(kv4.y);
            Kp[kb + 16] = f2tf(kv4.z);
            Kp[kb + 24] = f2tf(kv4.w);
            float4 vv = *(const float4*)(kvrow + 64 + dc);
            *(uint4*)(Vq + r * VSTRW + dc) =
                make_uint4(f2tf(vv.x), f2tf(vv.y), f2tf(vv.z), f2tf(vv.w));
        }
        __syncthreads();

        // ---- scores: Q @ K^T (warp: rows wm*32..+32, cols wn*32..+32) ----
        float sacc[2][4][4];
#pragma unroll
        for (int mt = 0; mt < 2; mt++)
#pragma unroll
            for (int nt = 0; nt < 4; nt++)
#pragma unroll
                for (int i = 0; i < 4; i++) sacc[mt][nt][i] = 0.f;

#pragma unroll
        for (int chunk = 0; chunk < 4; chunk++) {
            const int co = chunk * 32 + tig * 8;
            uint4 kf0[4], kf1[4];
#pragma unroll
            for (int nt = 0; nt < 4; nt++) {
                const int kb = (wn * 32 + nt * 8 + g) * KSTRW + co;
                kf0[nt] = *(const uint4*)(Kp + kb);
                kf1[nt] = *(const uint4*)(Kp + kb + 4);
            }
#pragma unroll
            for (int mt = 0; mt < 2; mt++) {
                const int ra = (wm * 32 + mt * 16 + g) * QSTRW + co;
                const uint4 qg0 = *(const uint4*)(Qp + ra);
                const uint4 qg1 = *(const uint4*)(Qp + ra + 4);
                const uint4 qh0 = *(const uint4*)(Qp + ra + 8 * QSTRW);
                const uint4 qh1 = *(const uint4*)(Qp + ra + 8 * QSTRW + 4);
                const uint32_t a0[4] = {qg0.x, qh0.x, qg0.y, qh0.y};
                const uint32_t a1[4] = {qg0.z, qh0.z, qg0.w, qh0.w};
                const uint32_t a2[4] = {qg1.x, qh1.x, qg1.y, qh1.y};
                const uint32_t a3[4] = {qg1.z, qh1.z, qg1.w, qh1.w};
#pragma unroll
                for (int nt = 0; nt < 4; nt++) {
                    const uint32_t b0[2] = {kf0[nt].x, kf0[nt].y};
                    const uint32_t b1[2] = {kf0[nt].z, kf0[nt].w};
                    const uint32_t b2[2] = {kf1[nt].x, kf1[nt].y};
                    const uint32_t b3[2] = {kf1[nt].z, kf1[nt].w};
                    mma_tf32(sacc[mt][nt], a0, b0);
                    mma_tf32(sacc[mt][nt], a1, b1);
                    mma_tf32(sacc[mt][nt], a2, b2);
                    mma_tf32(sacc[mt][nt], a3, b3);
                }
            }
        }

        // causal mask
        if (kt >= nkt - 2) {
#pragma unroll
            for (int mt = 0; mt < 2; mt++)
#pragma unroll
                for (int nt = 0; nt < 4; nt++) {
                    const int row = q0 + wm * 32 + mt * 16 + g;
                    const int col = k0 + wn * 32 + nt * 8 + 2 * tig;
                    if (col     > row)     sacc[mt][nt][0] = -1e30f;
                    if (col + 1 > row)     sacc[mt][nt][1] = -1e30f;
                    if (col     > row + 8) sacc[mt][nt][2] = -1e30f;
                    if (col + 1 > row + 8) sacc[mt][nt][3] = -1e30f;
                }
        }
        // store raw scores
#pragma unroll
        for (int mt = 0; mt < 2; mt++)
#pragma unroll
            for (int nt = 0; nt < 4; nt++) {
                const int lr = wm * 32 + mt * 16 + g;
                const int lc = wn * 32 + nt * 8 + 2 * tig;
                *(float2*)&Pf[lr * PSTRW + lc] =
                    make_float2(sacc[mt][nt][0], sacc[mt][nt][1]);
                *(float2*)&Pf[(lr + 8) * PSTRW + lc] =
                    make_float2(sacc[mt][nt][2], sacc[mt][nt][3]);
            }
        __syncthreads();

        // ---- online softmax: 2 threads per row, in-place tf32 permuted ----
        {
            const int row = t >> 1, half = t & 1;
            float vals[32];
            const float* pr = Pf + row * PSTRW + half * 32;
#pragma unroll
            for (int j = 0; j < 8; j++) {
                const float4 v4 = *(const float4*)(pr + j * 4);
                vals[j * 4 + 0] = v4.x; vals[j * 4 + 1] = v4.y;
                vals[j * 4 + 2] = v4.z; vals[j * 4 + 3] = v4.w;
            }
            const float mold = rm[row];
            float mx = mold;
#pragma unroll
            for (int c = 0; c < 32; c++) mx = fmaxf(mx, vals[c]);
            mx = fmaxf(mx, __shfl_xor_sync(0xffffffffu, mx, 1));
            const float f = __expf(mold - mx);
            float sum = 0.f;
            uint32_t* pw = Pu + row * PSTRW + half * 32;
#pragma unroll
            for (int c = 0; c < 32; c++) {
                const float p = __expf(vals[c] - mx);
                sum += p;
                pw[(c & 3) * 8 + (c >> 2)] = f2tf(p);
            }
            sum += __shfl_xor_sync(0xffffffffu, sum, 1);
            if (!half) { rm[row] = mx; rl[row] = rl[row] * f + sum; rf[row] = f; }
        }
        __syncthreads();

        // ---- rescale accumulators, then O += P @ V ----
#pragma unroll
        for (int mt = 0; mt < 2; mt++) {
            const int rbase = wm * 32 + mt * 16;
            const float f0 = rf[rbase + g];
            const float f1 = rf[rbase + g + 8];
#pragma unroll
            for (int nt = 0; nt < 8; nt++) {
                oacc[mt][nt][0] *= f0; oacc[mt][nt][1] *= f0;
                oacc[mt][nt][2] *= f1; oacc[mt][nt][3] *= f1;
            }
        }
#pragma unroll
        for (int ck = 0; ck < 2; ck++) {
            const int co = ck * 32 + tig * 8;
            uint4 pg0[2], pg1[2], ph0[2], ph1[2];
#pragma unroll
            for (int mt = 0; mt < 2; mt++) {
                const int pb = (wm * 32 + mt * 16 + g) * PSTRW + co;
                pg0[mt] = *(const uint4*)(Pu + pb);
                pg1[mt] = *(const uint4*)(Pu + pb + 4);
                ph0[mt] = *(const uint4*)(Pu + pb + 8 * PSTRW);
                ph1[mt] = *(const uint4*)(Pu + pb + 8 * PSTRW + 4);
            }
#pragma unroll
            for (int ks = 0; ks < 4; ks++) {
                const int krow = ck * 32 + ks * 8 + tig;
                uint32_t vb[8][2];
#pragma unroll
                for (int nt = 0; nt < 8; nt++) {
                    const int vcol = wn * 64 + nt * 8 + g;
                    vb[nt][0] = Vq[(size_t)krow * VSTRW + vcol];
                    vb[nt][1] = Vq[(size_t)(krow + 4) * VSTRW + vcol];
                }
#pragma unroll
                for (int mt = 0; mt < 2; mt++) {
                    uint32_t a[4];
                    if (ks == 0) { a[0]=pg0[mt].x; a[1]=ph0[mt].x; a[2]=pg0[mt].y; a[3]=ph0[mt].y; }
                    else if (ks == 1) { a[0]=pg0[mt].z; a[1]=ph0[mt].z; a[2]=pg0[mt].w; a[3]=ph0[mt].w; }
                    else if (ks == 2) { a[0]=pg1[mt].x; a[1]=ph1[mt].x; a[2]=pg1[mt].y; a[3]=ph1[mt].y; }
                    else              { a[0]=pg1[mt].z; a[1]=ph1[mt].z; a[2]=pg1[mt].w; a[3]=ph1[mt].w; }
#pragma unroll
                    for (int nt = 0; nt < 8; nt++)
                        mma_tf32(oacc[mt][nt], a, vb[nt]);
                }
            }
        }
    }

    __syncthreads();
    // epilogue
#pragma unroll
    for (int mt = 0; mt < 2; mt++) {
        const int rbase = wm * 32 + mt * 16;
        const float inv0 = 1.0f / rl[rbase + g];
        const float inv1 = 1.0f / rl[rbase + g + 8];
#pragma unroll
        for (int nt = 0; nt < 8; nt++) {
            const int col = wn * 64 + nt * 8 + 2 * tig;
            const size_t base0 =
                (((size_t)(b * SEQ + q0 + rbase + g) * 16 + h) << 7) + col;
            const size_t base1 =
                (((size_t)(b * SEQ + q0 + rbase + g + 8) * 16 + h) << 7) + col;
            *(float2*)(o + base0) =
                make_float2(oacc[mt][nt][0] * inv0, oacc[mt][nt][1] * inv0);
            *(float2*)(o + base1) =
                make_float2(oacc[mt][nt][2] * inv1, oacc[mt][nt][3] * inv1);
        }
    }
}

// ---------------------------------------------------------------------------
// Launch
// ---------------------------------------------------------------------------
extern "C" void kernel_launch(void* const* d_in, const int* in_sizes, int n_in,
                              void* d_out, int out_size)
{
    (void)in_sizes; (void)n_in; (void)out_size;
    const float* x          = (const float*)d_in[0];
    const float* w_query    = (const float*)d_in[1];
    const float* wkv_a      = (const float*)d_in[2];
    const float* wkv_b      = (const float*)d_in[3];
    const float* kv_norm_w  = (const float*)d_in[4];
    const float* out_proj_w = (const float*)d_in[5];
    float* out = (float*)d_out;

    float *q, *kv, *kvc, *kpe, *kvdec, *attn;
    cudaGetSymbolAddress((void**)&q,     g_q);
    cudaGetSymbolAddress((void**)&kv,    g_kv);
    cudaGetSymbolAddress((void**)&kvc,   g_kvc);
    cudaGetSymbolAddress((void**)&kpe,   g_kpe);
    cudaGetSymbolAddress((void**)&kvdec, g_kvdec);
    cudaGetSymbolAddress((void**)&attn,  g_attn);

    cudaFuncSetAttribute(gemm_tf32,
                         cudaFuncAttributeMaxDynamicSharedMemorySize, GEMM_SMEM);
    cudaFuncSetAttribute(flash_mma2,
                         cudaFuncAttributeMaxDynamicSharedMemorySize, FLASH_SMEM);

    // q = x @ w_query             [4096,2048]
    gemm_tf32<<<dim3(16, 32), 256, GEMM_SMEM>>>(x, w_query, q, TOKS, 2048, 2048);
    // kv = x @ wkv_a              [4096,576]
    gemm_tf32<<<dim3(5, 32), 256, GEMM_SMEM>>>(x, wkv_a, kv, TOKS, 576, 2048);
    // rope q_pe in place
    rope_q_kernel<<<TOKS, 512>>>(q);
    // rmsnorm latent
    rmsnorm_kernel<<<TOKS, 128>>>(kv, kv_norm_w, kvc);
    // rope k_pe
    rope_k_kernel<<<TOKS, 32>>>(kv, kpe);
    // kv_dec = c @ wkv_b          [4096,3072]
    gemm_tf32<<<dim3(24, 32), 256, GEMM_SMEM>>>(kvc, wkv_b, kvdec, TOKS, 3072, 512);
    // causal flash attention
    flash_mma2<<<dim3(SEQ / FQ, 16, 2), 256, FLASH_SMEM>>>(q, kvdec, kpe, attn);
    // out = attn @ out_proj_w     [4096,2048]
    gemm_tf32<<<dim3(16, 32), 256, GEMM_SMEM>>>(attn, out_proj_w, out, TOKS, 2048, 2048);
}

// round 6
// speedup vs baseline: 1.4041x; 1.4041x over previous
#include <cuda_runtime.h>
#include <math.h>
#include <stdint.h>

// B=2, S=2048, T=4096, D_IN=2048, H=16, QK_HEAD=128, V_HEAD=128, KV_RANK=512
#define TOKS 4096
#define SEQ  2048

// ---------------------------------------------------------------------------
// Scratch
// ---------------------------------------------------------------------------
__device__ float g_q[(size_t)TOKS * 2048];
__device__ float g_kv[(size_t)TOKS * 576];
__device__ float g_kvc[(size_t)TOKS * 512];     // rounded+permuted (gemm3 A)
__device__ float g_kpe[(size_t)TOKS * 64];
__device__ float g_kvdec[(size_t)TOKS * 3072];
__device__ float g_attn[(size_t)TOKS * 2048];   // rounded+permuted (gemm4 A)
__device__ float g_xr[(size_t)TOKS * 2048];     // x rounded+permuted
__device__ float g_wqT[(size_t)2048 * 2048];    // w_query^T rounded+permuted
__device__ float g_wkvaT[(size_t)640 * 2048];   // wkv_a^T (padded 576->640)
__device__ float g_wkvbT[(size_t)3072 * 512];   // wkv_b^T
__device__ float g_woutT[(size_t)2048 * 2048];  // out_proj^T

// ---------------------------------------------------------------------------
// Helpers
// ---------------------------------------------------------------------------
__device__ __forceinline__ uint32_t f2tf(float x) {
    uint32_t u;
    asm("cvt.rna.tf32.f32 %0, %1;" : "=r"(u) : "f"(x));
    return u;
}

__device__ __forceinline__ void mma_tf32(float* d, const uint32_t* a, const uint32_t* b) {
    asm volatile(
        "mma.sync.aligned.m16n8k8.row.col.f32.tf32.tf32.f32 "
        "{%0,%1,%2,%3}, {%4,%5,%6,%7}, {%8,%9}, {%0,%1,%2,%3};\n"
        : "+f"(d[0]), "+f"(d[1]), "+f"(d[2]), "+f"(d[3])
        : "r"(a[0]), "r"(a[1]), "r"(a[2]), "r"(a[3]), "r"(b[0]), "r"(b[1]));
}

__device__ __forceinline__ void cp_async16(void* smem_ptr, const void* gptr) {
    uint32_t saddr = (uint32_t)__cvta_generic_to_shared(smem_ptr);
    asm volatile("cp.async.cg.shared.global [%0], [%1], 16;\n"
                 :: "r"(saddr), "l"(gptr) : "memory");
}
__device__ __forceinline__ void cp_commit() {
    asm volatile("cp.async.commit_group;\n" ::: "memory");
}
template <int N>
__device__ __forceinline__ void cp_wait() {
    asm volatile("cp.async.wait_group %0;\n" :: "n"(N) : "memory");
}

// permute within a 32-word chunk: word c -> (c&3)*8 + (c>>2)
__device__ __forceinline__ int perm32(int c) { return (c & 3) * 8 + (c >> 2); }

// ---------------------------------------------------------------------------
// Pre-pass: round x to TF32 + permute each 32-col chunk.  (row width 2048)
// ---------------------------------------------------------------------------
__global__ __launch_bounds__(256)
void prep_x_kernel(const float* __restrict__ x, float* __restrict__ xr)
{
    const size_t e = ((size_t)blockIdx.x * 256 + threadIdx.x) * 4;
    const float4 v = *(const float4*)(x + e);
    uint32_t* out = (uint32_t*)xr + (e & ~(size_t)31) + ((e & 31) >> 2);
    out[0]  = f2tf(v.x);
    out[8]  = f2tf(v.y);
    out[16] = f2tf(v.z);
    out[24] = f2tf(v.w);
}

// ---------------------------------------------------------------------------
// Pre-pass: weight [K][N] -> [Npad][K], rounded, k-chunks permuted.
// grid (Npad/32, K/32), block (32,8). Pad rows (n>=N) are zero.
// ---------------------------------------------------------------------------
__global__ void prep_weight_kernel(const float* __restrict__ w, float* __restrict__ wt,
                                   int K, int N)
{
    __shared__ float tile[32][33];
    const int n0 = blockIdx.x * 32, k0 = blockIdx.y * 32;
    const int tx = threadIdx.x, ty = threadIdx.y;
    const int n = n0 + tx;
#pragma unroll
    for (int i = ty; i < 32; i += 8)
        tile[i][tx] = (n < N) ? w[(size_t)(k0 + i) * N + n] : 0.f;
    __syncthreads();
    const int p = perm32(tx);
#pragma unroll
    for (int i = ty; i < 32; i += 8) {
        uint32_t* o = (uint32_t*)wt + (size_t)(n0 + i) * K + k0 + p;
        *o = f2tf(tile[tx][i]);
    }
}

// ---------------------------------------------------------------------------
// TF32 GEMM v3: C[M,N] = A[M,K] @ B[K,N].
// A: g-layout [M][K] rounded+permuted.  Bt: [Npad][K] rounded+permuted.
// BM=BN=128, BK=32, 256 thr / 8 warps (warp tile 64x32).
// Smem: As [128][36], Bs [128][36]; all fragments LDS.128, conflict-free.
// cp.async double-buffered. No cvt anywhere in the kernel.
// ---------------------------------------------------------------------------
#define G_STR 36
#define G_BUFW (128 * G_STR)
#define GEMM_SMEM (4 * G_BUFW * 4)

__device__ __forceinline__ void gemm_stage(const float* __restrict__ A,
                                           const float* __restrict__ Bt,
                                           uint32_t* As, uint32_t* Bs,
                                           int row0, int col0, int k0,
                                           int K, int t)
{
#pragma unroll
    for (int i = 0; i < 4; i++) {
        const int id = t + i * 256;          // 1024 16B chunks each
        const int r = id >> 3, c = (id & 7) * 4;
        cp_async16(As + r * G_STR + c, A  + (size_t)(row0 + r) * K + k0 + c);
        cp_async16(Bs + r * G_STR + c, Bt + (size_t)(col0 + r) * K + k0 + c);
    }
}

__global__ __launch_bounds__(256)
void gemm_tf32(const float* __restrict__ A, const float* __restrict__ Bt,
               float* __restrict__ C, int M, int N, int K)
{
    extern __shared__ uint32_t smw[];
    uint32_t* AsB[2] = { smw, smw + 2 * G_BUFW };
    uint32_t* BsB[2] = { smw + G_BUFW, smw + 3 * G_BUFW };

    const int t = threadIdx.x;
    const int lane = t & 31, wid = t >> 5;
    const int g = lane >> 2, tig = lane & 3;
    const int wm = wid >> 2;      // 0..1 -> 64 rows
    const int wn = wid & 3;       // 0..3 -> 32 cols
    const int row0 = blockIdx.y * 128;
    const int col0 = blockIdx.x * 128;

    float acc[4][4][4];
#pragma unroll
    for (int mt = 0; mt < 4; mt++)
#pragma unroll
        for (int nt = 0; nt < 4; nt++)
#pragma unroll
            for (int i = 0; i < 4; i++) acc[mt][nt][i] = 0.f;

    const int nkt = K >> 5;
    gemm_stage(A, Bt, AsB[0], BsB[0], row0, col0, 0, K, t);
    cp_commit();

    for (int kt = 0; kt < nkt; kt++) {
        if (kt + 1 < nkt) {
            gemm_stage(A, Bt, AsB[(kt + 1) & 1], BsB[(kt + 1) & 1],
                       row0, col0, (kt + 1) << 5, K, t);
            cp_commit();
            cp_wait<1>();
        } else {
            cp_wait<0>();
        }
        __syncthreads();

        const uint32_t* Aq = AsB[kt & 1];
        const uint32_t* Bq = BsB[kt & 1];

        uint4 b0[4], b1[4];
#pragma unroll
        for (int nt = 0; nt < 4; nt++) {
            const uint32_t* bp = Bq + (wn * 32 + nt * 8 + g) * G_STR + tig * 8;
            b0[nt] = *(const uint4*)bp;
            b1[nt] = *(const uint4*)(bp + 4);
        }
#pragma unroll
        for (int mt = 0; mt < 4; mt++) {
            const uint32_t* ap = Aq + (wm * 64 + mt * 16 + g) * G_STR + tig * 8;
            const uint4 ag0 = *(const uint4*)ap;
            const uint4 ag1 = *(const uint4*)(ap + 4);
            const uint4 ah0 = *(const uint4*)(ap + 8 * G_STR);
            const uint4 ah1 = *(const uint4*)(ap + 8 * G_STR + 4);
            const uint32_t a0[4] = {ag0.x, ah0.x, ag0.y, ah0.y};
            const uint32_t a1[4] = {ag0.z, ah0.z, ag0.w, ah0.w};
            const uint32_t a2[4] = {ag1.x, ah1.x, ag1.y, ah1.y};
            const uint32_t a3[4] = {ag1.z, ah1.z, ag1.w, ah1.w};
#pragma unroll
            for (int nt = 0; nt < 4; nt++) {
                const uint32_t p0[2] = {b0[nt].x, b0[nt].y};
                const uint32_t p1[2] = {b0[nt].z, b0[nt].w};
                const uint32_t p2[2] = {b1[nt].x, b1[nt].y};
                const uint32_t p3[2] = {b1[nt].z, b1[nt].w};
                mma_tf32(acc[mt][nt], a0, p0);
                mma_tf32(acc[mt][nt], a1, p1);
                mma_tf32(acc[mt][nt], a2, p2);
                mma_tf32(acc[mt][nt], a3, p3);
            }
        }
        __syncthreads();
    }

#pragma unroll
    for (int mt = 0; mt < 4; mt++) {
        const int gr0 = row0 + wm * 64 + mt * 16 + g;
#pragma unroll
        for (int nt = 0; nt < 4; nt++) {
            const int gc = col0 + wn * 32 + nt * 8 + 2 * tig;
            if (gc < N) {
                *(float2*)(C + (size_t)gr0 * N + gc) =
                    make_float2(acc[mt][nt][0], acc[mt][nt][1]);
                *(float2*)(C + (size_t)(gr0 + 8) * N + gc) =
                    make_float2(acc[mt][nt][2], acc[mt][nt][3]);
            }
        }
    }
}

// ---------------------------------------------------------------------------
// RMSNorm over 512 latent dims; output rounded+permuted (feeds gemm3 as A).
// ---------------------------------------------------------------------------
__global__ __launch_bounds__(128)
void rmsnorm_kernel(const float* __restrict__ kv, const float* __restrict__ w,
                    float* __restrict__ out)
{
    __shared__ float red[4];
    const int tok = blockIdx.x;
    const int t = threadIdx.x;
    const float* row = kv + (size_t)tok * 576;
    float v[4];
    float s = 0.0f;
#pragma unroll
    for (int u = 0; u < 4; u++) {
        v[u] = row[t + u * 128];
        s = fmaf(v[u], v[u], s);
    }
#pragma unroll
    for (int off = 16; off > 0; off >>= 1)
        s += __shfl_down_sync(0xffffffffu, s, off);
    if ((t & 31) == 0) red[t >> 5] = s;
    __syncthreads();
    const float tot = red[0] + red[1] + red[2] + red[3];
    const float r = rsqrtf(tot * (1.0f / 512.0f) + 1e-6f);
    uint32_t* orow = (uint32_t*)(out + (size_t)tok * 512);
#pragma unroll
    for (int u = 0; u < 4; u++) {
        const int idx = t + u * 128;
        orow[(idx & ~31) + perm32(idx & 31)] = f2tf(v[u] * r * w[idx]);
    }
}

// ---------------------------------------------------------------------------
// RoPE
// ---------------------------------------------------------------------------
__global__ __launch_bounds__(512)
void rope_q_kernel(float* __restrict__ q)
{
    const int tok = blockIdx.x;
    const int h = threadIdx.x >> 5;
    const int i = threadIdx.x & 31;
    const int s = tok & (SEQ - 1);
    const float e = (float)(2 * i) * (1.0f / 64.0f);
    const float freq = 1.0f / powf(10000.0f, e);
    float sn, c;
    sincosf((float)s * freq, &sn, &c);
    float* base = q + ((size_t)tok * 16 + h) * 128 + 64;
    const float x1 = base[2 * i];
    const float x2 = base[2 * i + 1];
    base[2 * i]     = x1 * c - x2 * sn;
    base[2 * i + 1] = x2 * c + x1 * sn;
}

__global__ __launch_bounds__(32)
void rope_k_kernel(const float* __restrict__ kv, float* __restrict__ kpe)
{
    const int tok = blockIdx.x;
    const int i = threadIdx.x;
    const int s = tok & (SEQ - 1);
    const float e = (float)(2 * i) * (1.0f / 64.0f);
    const float freq = 1.0f / powf(10000.0f, e);
    float sn, c;
    sincosf((float)s * freq, &sn, &c);
    const float* src = kv + (size_t)tok * 576 + 512;
    const float x1 = src[2 * i];
    const float x2 = src[2 * i + 1];
    kpe[(size_t)tok * 64 + 2 * i]     = x1 * c - x2 * sn;
    kpe[(size_t)tok * 64 + 2 * i + 1] = x2 * c + x1 * sn;
}

// ---------------------------------------------------------------------------
// Flash attention (causal, TF32 mma). 128q x 64k, d=128, 8 warps.
// Q/K permuted TF32 in smem; V raw TF32; P in-place permuted TF32.
// Epilogue writes attn rounded+permuted (feeds gemm4 as A).
// ---------------------------------------------------------------------------
#define FQ 128
#define FKEY 64
#define QSTRW 132
#define KSTRW 132
#define VSTRW 136
#define PSTRW 68
#define SM_KP (FQ * QSTRW)
#define SM_VQ (SM_KP + FKEY * KSTRW)
#define SM_P  (SM_VQ + FKEY * VSTRW)
#define SM_RM (SM_P + FQ * PSTRW)
#define FLASH_SMEM ((SM_RM + 3 * FQ) * 4)

__global__ __launch_bounds__(256)
void flash_mma2(const float* __restrict__ q, const float* __restrict__ kvdec,
                const float* __restrict__ kpe, float* __restrict__ o)
{
    extern __shared__ uint32_t smw[];
    uint32_t* Qp = smw;
    uint32_t* Kp = smw + SM_KP;
    uint32_t* Vq = smw + SM_VQ;
    float*    Pf = (float*)(smw + SM_P);
    uint32_t* Pu = smw + SM_P;
    float* rm = (float*)(smw + SM_RM);
    float* rl = rm + FQ;
    float* rf = rl + FQ;

    const int t = threadIdx.x;
    const int lane = t & 31, wid = t >> 5;
    const int g = lane >> 2, tig = lane & 3;
    const int wm = wid >> 1;
    const int wn = wid & 1;
    const int qb = blockIdx.x, h = blockIdx.y, b = blockIdx.z;
    const int q0 = qb * FQ;
    const float scale = 0.08838834764831845f;

#pragma unroll
    for (int i = 0; i < 16; i++) {
        const int id = t + i * 256;
        const int r = id >> 5, dc = (id & 31) * 4;
        float4 v = *(const float4*)(q + (((size_t)(b * SEQ + q0 + r) * 16 + h) << 7) + dc);
        const int base = r * QSTRW + (dc & 96) + ((dc & 31) >> 2);
        Qp[base + 0]  = f2tf(v.x * scale);
        Qp[base + 8]  = f2tf(v.y * scale);
        Qp[base + 16] = f2tf(v.z * scale);
        Qp[base + 24] = f2tf(v.w * scale);
    }
    if (t < FQ) { rm[t] = -1e30f; rl[t] = 0.f; }

    float oacc[2][8][4];
#pragma unroll
    for (int mt = 0; mt < 2; mt++)
#pragma unroll
        for (int nt = 0; nt < 8; nt++)
#pragma unroll
            for (int i = 0; i < 4; i++) oacc[mt][nt][i] = 0.f;

    const int nkt = 2 * (qb + 1);
    for (int kt = 0; kt < nkt; kt++) {
        __syncthreads();
        const int k0 = kt * FKEY;
#pragma unroll
        for (int i = 0; i < 8; i++) {
            const int id = t + i * 256;
            const int r = id >> 5, dc = (id & 31) * 4;
            const size_t tok = (size_t)(b * SEQ + k0 + r);
            const float* kvrow = kvdec + (tok * 16 + h) * 192;
            float4 kv4 = (dc < 64) ? *(const float4*)(kvrow + dc)
                                   : *(const float4*)(kpe + tok * 64 + (dc - 64));
            const int kb = r * KSTRW + (dc & 96) + ((dc & 31) >> 2);
            Kp[kb + 0]  = f2tf(kv4.x);
            Kp[kb + 8]  = f2tf(kv4.y);
            Kp[kb + 16] = f2tf(kv4.z);
            Kp[kb + 24] = f2tf(kv4.w);
            float4 vv = *(const float4*)(kvrow + 64 + dc);
            *(uint4*)(Vq + r * VSTRW + dc) =
                make_uint4(f2tf(vv.x), f2tf(vv.y), f2tf(vv.z), f2tf(vv.w));
        }
        __syncthreads();

        float sacc[2][4][4];
#pragma unroll
        for (int mt = 0; mt < 2; mt++)
#pragma unroll
            for (int nt = 0; nt < 4; nt++)
#pragma unroll
                for (int i = 0; i < 4; i++) sacc[mt][nt][i] = 0.f;

#pragma unroll
        for (int chunk = 0; chunk < 4; chunk++) {
            const int co = chunk * 32 + tig * 8;
            uint4 kf0[4], kf1[4];
#pragma unroll
            for (int nt = 0; nt < 4; nt++) {
                const int kb = (wn * 32 + nt * 8 + g) * KSTRW + co;
                kf0[nt] = *(const uint4*)(Kp + kb);
                kf1[nt] = *(const uint4*)(Kp + kb + 4);
            }
#pragma unroll
            for (int mt = 0; mt < 2; mt++) {
                const int ra = (wm * 32 + mt * 16 + g) * QSTRW + co;
                const uint4 qg0 = *(const uint4*)(Qp + ra);
                const uint4 qg1 = *(const uint4*)(Qp + ra + 4);
                const uint4 qh0 = *(const uint4*)(Qp + ra + 8 * QSTRW);
                const uint4 qh1 = *(const uint4*)(Qp + ra + 8 * QSTRW + 4);
                const uint32_t a0[4] = {qg0.x, qh0.x, qg0.y, qh0.y};
                const uint32_t a1[4] = {qg0.z, qh0.z, qg0.w, qh0.w};
                const uint32_t a2[4] = {qg1.x, qh1.x, qg1.y, qh1.y};
                const uint32_t a3[4] = {qg1.z, qh1.z, qg1.w, qh1.w};
#pragma unroll
                for (int nt = 0; nt < 4; nt++) {
                    const uint32_t b0[2] = {kf0[nt].x, kf0[nt].y};
                    const uint32_t b1[2] = {kf0[nt].z, kf0[nt].w};
                    const uint32_t b2[2] = {kf1[nt].x, kf1[nt].y};
                    const uint32_t b3[2] = {kf1[nt].z, kf1[nt].w};
                    mma_tf32(sacc[mt][nt], a0, b0);
                    mma_tf32(sacc[mt][nt], a1, b1);
                    mma_tf32(sacc[mt][nt], a2, b2);
                    mma_tf32(sacc[mt][nt], a3, b3);
                }
            }
        }

        if (kt >= nkt - 2) {
#pragma unroll
            for (int mt = 0; mt < 2; mt++)
#pragma unroll
                for (int nt = 0; nt < 4; nt++) {
                    const int row = q0 + wm * 32 + mt * 16 + g;
                    const int col = k0 + wn * 32 + nt * 8 + 2 * tig;
                    if (col     > row)     sacc[mt][nt][0] = -1e30f;
                    if (col + 1 > row)     sacc[mt][nt][1] = -1e30f;
                    if (col     > row + 8) sacc[mt][nt][2] = -1e30f;
                    if (col + 1 > row + 8) sacc[mt][nt][3] = -1e30f;
                }
        }
#pragma unroll
        for (int mt = 0; mt < 2; mt++)
#pragma unroll
            for (int nt = 0; nt < 4; nt++) {
                const int lr = wm * 32 + mt * 16 + g;
                const int lc = wn * 32 + nt * 8 + 2 * tig;
                *(float2*)&Pf[lr * PSTRW + lc] =
                    make_float2(sacc[mt][nt][0], sacc[mt][nt][1]);
                *(float2*)&Pf[(lr + 8) * PSTRW + lc] =
                    make_float2(sacc[mt][nt][2], sacc[mt][nt][3]);
            }
        __syncthreads();

        {
            const int row = t >> 1, half = t & 1;
            float vals[32];
            const float* pr = Pf + row * PSTRW + half * 32;
#pragma unroll
            for (int j = 0; j < 8; j++) {
                const float4 v4 = *(const float4*)(pr + j * 4);
                vals[j * 4 + 0] = v4.x; vals[j * 4 + 1] = v4.y;
                vals[j * 4 + 2] = v4.z; vals[j * 4 + 3] = v4.w;
            }
            const float mold = rm[row];
            float mx = mold;
#pragma unroll
            for (int c = 0; c < 32; c++) mx = fmaxf(mx, vals[c]);
            mx = fmaxf(mx, __shfl_xor_sync(0xffffffffu, mx, 1));
            const float f = __expf(mold - mx);
            float sum = 0.f;
            uint32_t* pw = Pu + row * PSTRW + half * 32;
#pragma unroll
            for (int c = 0; c < 32; c++) {
                const float p = __expf(vals[c] - mx);
                sum += p;
                pw[(c & 3) * 8 + (c >> 2)] = f2tf(p);
            }
            sum += __shfl_xor_sync(0xffffffffu, sum, 1);
            if (!half) { rm[row] = mx; rl[row] = rl[row] * f + sum; rf[row] = f; }
        }
        __syncthreads();

#pragma unroll
        for (int mt = 0; mt < 2; mt++) {
            const int rbase = wm * 32 + mt * 16;
            const float f0 = rf[rbase + g];
            const float f1 = rf[rbase + g + 8];
#pragma unroll
            for (int nt = 0; nt < 8; nt++) {
                oacc[mt][nt][0] *= f0; oacc[mt][nt][1] *= f0;
                oacc[mt][nt][2] *= f1; oacc[mt][nt][3] *= f1;
            }
        }
#pragma unroll
        for (int ck = 0; ck < 2; ck++) {
            const int co = ck * 32 + tig * 8;
            uint4 pg0[2], pg1[2], ph0[2], ph1[2];
#pragma unroll
            for (int mt = 0; mt < 2; mt++) {
                const int pb = (wm * 32 + mt * 16 + g) * PSTRW + co;
                pg0[mt] = *(const uint4*)(Pu + pb);
                pg1[mt] = *(const uint4*)(Pu + pb + 4);
                ph0[mt] = *(const uint4*)(Pu + pb + 8 * PSTRW);
                ph1[mt] = *(const uint4*)(Pu + pb + 8 * PSTRW + 4);
            }
#pragma unroll
            for (int ks = 0; ks < 4; ks++) {
                const int krow = ck * 32 + ks * 8 + tig;
                uint32_t vb[8][2];
#pragma unroll
                for (int nt = 0; nt < 8; nt++) {
                    const int vcol = wn * 64 + nt * 8 + g;
                    vb[nt][0] = Vq[(size_t)krow * VSTRW + vcol];
                    vb[nt][1] = Vq[(size_t)(krow + 4) * VSTRW + vcol];
                }
#pragma unroll
                for (int mt = 0; mt < 2; mt++) {
                    uint32_t a[4];
                    if (ks == 0) { a[0]=pg0[mt].x; a[1]=ph0[mt].x; a[2]=pg0[mt].y; a[3]=ph0[mt].y; }
                    else if (ks == 1) { a[0]=pg0[mt].z; a[1]=ph0[mt].z; a[2]=pg0[mt].w; a[3]=ph0[mt].w; }
                    else if (ks == 2) { a[0]=pg1[mt].x; a[1]=ph1[mt].x; a[2]=pg1[mt].y; a[3]=ph1[mt].y; }
                    else              { a[0]=pg1[mt].z; a[1]=ph1[mt].z; a[2]=pg1[mt].w; a[3]=ph1[mt].w; }
#pragma unroll
                    for (int nt = 0; nt < 8; nt++)
                        mma_tf32(oacc[mt][nt], a, vb[nt]);
                }
            }
        }
    }

    __syncthreads();
    // epilogue: divide by l, round to TF32, store PERMUTED (gemm4 A layout)
    uint32_t* ou = (uint32_t*)o;
#pragma unroll
    for (int mt = 0; mt < 2; mt++) {
        const int rbase = wm * 32 + mt * 16;
        const float inv0 = 1.0f / rl[rbase + g];
        const float inv1 = 1.0f / rl[rbase + g + 8];
#pragma unroll
        for (int nt = 0; nt < 8; nt++) {
            const int col = wn * 64 + nt * 8 + 2 * tig;   // within-head col
            const int poff = (col & ~31) + perm32(col & 31);
            const size_t r0 = (((size_t)(b * SEQ + q0 + rbase + g) * 16 + h) << 7);
            const size_t r1 = (((size_t)(b * SEQ + q0 + rbase + g + 8) * 16 + h) << 7);
            ou[r0 + poff]     = f2tf(oacc[mt][nt][0] * inv0);
            ou[r0 + poff + 8] = f2tf(oacc[mt][nt][1] * inv0);
            ou[r1 + poff]     = f2tf(oacc[mt][nt][2] * inv1);
            ou[r1 + poff + 8] = f2tf(oacc[mt][nt][3] * inv1);
        }
    }
}

// ---------------------------------------------------------------------------
// Launch
// ---------------------------------------------------------------------------
extern "C" void kernel_launch(void* const* d_in, const int* in_sizes, int n_in,
                              void* d_out, int out_size)
{
    (void)in_sizes; (void)n_in; (void)out_size;
    const float* x          = (const float*)d_in[0];
    const float* w_query    = (const float*)d_in[1];
    const float* wkv_a      = (const float*)d_in[2];
    const float* wkv_b      = (const float*)d_in[3];
    const float* kv_norm_w  = (const float*)d_in[4];
    const float* out_proj_w = (const float*)d_in[5];
    float* out = (float*)d_out;

    float *q, *kv, *kvc, *kpe, *kvdec, *attn, *xr, *wqT, *wkvaT, *wkvbT, *woutT;
    cudaGetSymbolAddress((void**)&q,     g_q);
    cudaGetSymbolAddress((void**)&kv,    g_kv);
    cudaGetSymbolAddress((void**)&kvc,   g_kvc);
    cudaGetSymbolAddress((void**)&kpe,   g_kpe);
    cudaGetSymbolAddress((void**)&kvdec, g_kvdec);
    cudaGetSymbolAddress((void**)&attn,  g_attn);
    cudaGetSymbolAddress((void**)&xr,    g_xr);
    cudaGetSymbolAddress((void**)&wqT,   g_wqT);
    cudaGetSymbolAddress((void**)&wkvaT, g_wkvaT);
    cudaGetSymbolAddress((void**)&wkvbT, g_wkvbT);
    cudaGetSymbolAddress((void**)&woutT, g_woutT);

    cudaFuncSetAttribute(gemm_tf32,
                         cudaFuncAttributeMaxDynamicSharedMemorySize, GEMM_SMEM);
    cudaFuncSetAttribute(flash_mma2,
                         cudaFuncAttributeMaxDynamicSharedMemorySize, FLASH_SMEM);

    // --- pre-passes: round/permute x; transpose+round+permute weights ---
    prep_x_kernel<<<(TOKS * 2048) / (256 * 4), 256>>>(x, xr);
    prep_weight_kernel<<<dim3(2048 / 32, 2048 / 32), dim3(32, 8)>>>(w_query, wqT, 2048, 2048);
    prep_weight_kernel<<<dim3(640 / 32,  2048 / 32), dim3(32, 8)>>>(wkv_a, wkvaT, 2048, 576);
    prep_weight_kernel<<<dim3(3072 / 32, 512 / 32),  dim3(32, 8)>>>(wkv_b, wkvbT, 512, 3072);
    prep_weight_kernel<<<dim3(2048 / 32, 2048 / 32), dim3(32, 8)>>>(out_proj_w, woutT, 2048, 2048);

    // q = x @ w_query
    gemm_tf32<<<dim3(16, 32), 256, GEMM_SMEM>>>(xr, wqT, q, TOKS, 2048, 2048);
    // kv = x @ wkv_a
    gemm_tf32<<<dim3(5, 32), 256, GEMM_SMEM>>>(xr, wkvaT, kv, TOKS, 576, 2048);
    // rope q_pe in place
    rope_q_kernel<<<TOKS, 512>>>(q);
    // rmsnorm latent -> kvc (rounded+permuted)
    rmsnorm_kernel<<<TOKS, 128>>>(kv, kv_norm_w, kvc);
    // rope k_pe
    rope_k_kernel<<<TOKS, 32>>>(kv, kpe);
    // kv_dec = kvc @ wkv_b
    gemm_tf32<<<dim3(24, 32), 256, GEMM_SMEM>>>(kvc, wkvbT, kvdec, TOKS, 3072, 512);
    // causal flash attention -> attn (rounded+permuted)
    flash_mma2<<<dim3(SEQ / FQ, 16, 2), 256, FLASH_SMEM>>>(q, kvdec, kpe, attn);
    // out = attn @ out_proj_w
    gemm_tf32<<<dim3(16, 32), 256, GEMM_SMEM>>>(attn, woutT, out, TOKS, 2048, 2048);
}

// round 7
// speedup vs baseline: 2.7875x; 1.9853x over previous
#include <cuda_runtime.h>
#include <cuda_fp16.h>
#include <math.h>
#include <stdint.h>

// B=2, S=2048, T=4096, D_IN=2048, H=16, QK_HEAD=128, V_HEAD=128, KV_RANK=512
#define TOKS 4096
#define SEQ  2048

// ---------------------------------------------------------------------------
// Scratch (fp16 everywhere; fp32 accumulation inside kernels)
// ---------------------------------------------------------------------------
__device__ __half g_xh[(size_t)TOKS * 2048];
__device__ __half g_qh[(size_t)TOKS * 2048];
__device__ __half g_kvh[(size_t)TOKS * 576];
__device__ __half g_kvch[(size_t)TOKS * 512];
__device__ __half g_kpeh[(size_t)TOKS * 64];
__device__ __half g_kvdech[(size_t)TOKS * 3072];
__device__ __half g_attnh[(size_t)TOKS * 2048];
__device__ __half g_wqh[(size_t)2048 * 2048];
__device__ __half g_wkvah[(size_t)2048 * 576];
__device__ __half g_wkvbh[(size_t)512 * 3072];
__device__ __half g_wouth[(size_t)2048 * 2048];

// ---------------------------------------------------------------------------
// Helpers
// ---------------------------------------------------------------------------
__device__ __forceinline__ void mma_f16(float* d, const uint32_t* a, const uint32_t* b) {
    asm volatile(
        "mma.sync.aligned.m16n8k16.row.col.f32.f16.f16.f32 "
        "{%0,%1,%2,%3}, {%4,%5,%6,%7}, {%8,%9}, {%0,%1,%2,%3};\n"
        : "+f"(d[0]), "+f"(d[1]), "+f"(d[2]), "+f"(d[3])
        : "r"(a[0]), "r"(a[1]), "r"(a[2]), "r"(a[3]), "r"(b[0]), "r"(b[1]));
}

__device__ __forceinline__ void ldsm_x4(uint32_t* r, uint32_t addr) {
    asm volatile("ldmatrix.sync.aligned.m8n8.x4.shared.b16 {%0,%1,%2,%3}, [%4];\n"
                 : "=r"(r[0]), "=r"(r[1]), "=r"(r[2]), "=r"(r[3]) : "r"(addr));
}
__device__ __forceinline__ void ldsm_x4_t(uint32_t* r, uint32_t addr) {
    asm volatile("ldmatrix.sync.aligned.m8n8.x4.trans.shared.b16 {%0,%1,%2,%3}, [%4];\n"
                 : "=r"(r[0]), "=r"(r[1]), "=r"(r[2]), "=r"(r[3]) : "r"(addr));
}

__device__ __forceinline__ void cp_async16z(void* smem_ptr, const void* gptr, int sz) {
    uint32_t saddr = (uint32_t)__cvta_generic_to_shared(smem_ptr);
    asm volatile("cp.async.cg.shared.global [%0], [%1], 16, %2;\n"
                 :: "r"(saddr), "l"(gptr), "r"(sz) : "memory");
}
__device__ __forceinline__ void cp_commit() {
    asm volatile("cp.async.commit_group;\n" ::: "memory");
}
template <int N>
__device__ __forceinline__ void cp_wait() {
    asm volatile("cp.async.wait_group %0;\n" :: "n"(N) : "memory");
}

// ---------------------------------------------------------------------------
// Pre-pass: fp32 -> fp16 elementwise (optional scale). n4 = count/4.
// ---------------------------------------------------------------------------
__global__ __launch_bounds__(256)
void prep_half(const float* __restrict__ in, __half* __restrict__ out,
               float scale, int n4)
{
    const int i = blockIdx.x * 256 + threadIdx.x;
    if (i >= n4) return;
    const float4 v = ((const float4*)in)[i];
    __half2* o = (__half2*)out + (size_t)i * 2;
    o[0] = __floats2half2_rn(v.x * scale, v.y * scale);
    o[1] = __floats2half2_rn(v.z * scale, v.w * scale);
}

// ---------------------------------------------------------------------------
// FP16 GEMM: C[M,N] = A[M,K] @ B[K,N]. A fp16 [M][K]; B fp16 [K][N] natural.
// BM=BN=128, BK=32, 256 thr / 8 warps (warp tile 64x32). mma m16n8k16.
// A frags: ldmatrix.x4 on As[m][k] (stride 40 halves = 80B, phase-clean).
// B frags: ldmatrix.x4.trans on Bs[k][n] (stride 136 halves = 272B).
// cp.async double-buffered; zfill guard handles the N=576 tail.
// ---------------------------------------------------------------------------
#define GA_STR 40
#define GB_STR 136
#define GA_H (128 * GA_STR)   // 5120 halves
#define GB_H (32 * GB_STR)    // 4352 halves
#define GEMM_SMEM ((2 * GA_H + 2 * GB_H) * 2)   // 37888 B

template <bool HALF_OUT>
__global__ __launch_bounds__(256)
void gemm_f16(const __half* __restrict__ A, const __half* __restrict__ B,
              void* __restrict__ Cv, int M, int N, int K)
{
    extern __shared__ __half smh[];
    const uint32_t smb = (uint32_t)__cvta_generic_to_shared(smh);

    const int t = threadIdx.x;
    const int lane = t & 31, wid = t >> 5;
    const int g = lane >> 2, tig = lane & 3;
    const int wm = wid >> 2;      // 0..1 -> 64 rows
    const int wn = wid & 3;       // 0..3 -> 32 cols
    const int row0 = blockIdx.y * 128;
    const int col0 = blockIdx.x * 128;

    float acc[4][4][4];
#pragma unroll
    for (int mt = 0; mt < 4; mt++)
#pragma unroll
        for (int nt = 0; nt < 4; nt++)
#pragma unroll
            for (int i = 0; i < 4; i++) acc[mt][nt][i] = 0.f;

    const int nkt = K >> 5;

#define G_STAGE(buf, k0)                                                       \
    {                                                                          \
        __half* As = smh + (buf) * GA_H;                                       \
        __half* Bs = smh + 2 * GA_H + (buf) * GB_H;                            \
        _Pragma("unroll")                                                      \
        for (int i = 0; i < 2; i++) {                                          \
            const int id = t + i * 256;                                        \
            const int ar = id >> 2, ac = (id & 3) * 8;                         \
            cp_async16z(As + ar * GA_STR + ac,                                 \
                        A + (size_t)(row0 + ar) * K + (k0) + ac, 16);          \
            const int kr = id >> 4, nc = (id & 15) * 8;                        \
            const int col = col0 + nc;                                         \
            const int sz = (col + 8 <= N) ? 16 : 0;                            \
            cp_async16z(Bs + kr * GB_STR + nc,                                 \
                        B + (size_t)((k0) + kr) * N + (sz ? col : 0), sz);     \
        }                                                                      \
    }

    G_STAGE(0, 0);
    cp_commit();

    for (int kt = 0; kt < nkt; kt++) {
        if (kt + 1 < nkt) {
            G_STAGE((kt + 1) & 1, (kt + 1) << 5);
            cp_commit();
            cp_wait<1>();
        } else {
            cp_wait<0>();
        }
        __syncthreads();

        const uint32_t asb = smb + ((kt & 1) * GA_H) * 2;
        const uint32_t bsb = smb + (2 * GA_H + (kt & 1) * GB_H) * 2;

        // B fragments: one x4.trans per nt covers all 32 k (two ks steps)
        uint32_t bf[4][2][2];
        const uint32_t baddr = bsb + ((uint32_t)(lane * GB_STR + wn * 32)) * 2;
#pragma unroll
        for (int nt = 0; nt < 4; nt++) {
            uint32_t rr[4];
            ldsm_x4_t(rr, baddr + nt * 16);
            bf[nt][0][0] = rr[0]; bf[nt][0][1] = rr[1];
            bf[nt][1][0] = rr[2]; bf[nt][1][1] = rr[3];
        }
        const uint32_t aaddr =
            asb + ((uint32_t)((wm * 64 + (lane & 15)) * GA_STR + (lane >> 4) * 8)) * 2;
#pragma unroll
        for (int mt = 0; mt < 4; mt++) {
            uint32_t a0[4], a1[4];
            ldsm_x4(a0, aaddr + mt * (16 * GA_STR * 2));
            ldsm_x4(a1, aaddr + mt * (16 * GA_STR * 2) + 32);
#pragma unroll
            for (int nt = 0; nt < 4; nt++) {
                mma_f16(acc[mt][nt], a0, bf[nt][0]);
                mma_f16(acc[mt][nt], a1, bf[nt][1]);
            }
        }
        __syncthreads();
    }

#pragma unroll
    for (int mt = 0; mt < 4; mt++) {
        const int gr0 = row0 + wm * 64 + mt * 16 + g;
#pragma unroll
        for (int nt = 0; nt < 4; nt++) {
            const int gc = col0 + wn * 32 + nt * 8 + 2 * tig;
            if (gc < N) {
                if (HALF_OUT) {
                    __half* C = (__half*)Cv;
                    *(__half2*)(C + (size_t)gr0 * N + gc) =
                        __floats2half2_rn(acc[mt][nt][0], acc[mt][nt][1]);
                    *(__half2*)(C + (size_t)(gr0 + 8) * N + gc) =
                        __floats2half2_rn(acc[mt][nt][2], acc[mt][nt][3]);
                } else {
                    float* C = (float*)Cv;
                    *(float2*)(C + (size_t)gr0 * N + gc) =
                        make_float2(acc[mt][nt][0], acc[mt][nt][1]);
                    *(float2*)(C + (size_t)(gr0 + 8) * N + gc) =
                        make_float2(acc[mt][nt][2], acc[mt][nt][3]);
                }
            }
        }
    }
}

// ---------------------------------------------------------------------------
// RMSNorm over 512 latent dims (fp16 in/out, fp32 math)
// ---------------------------------------------------------------------------
__global__ __launch_bounds__(128)
void rmsnorm_h(const __half* __restrict__ kv, const float* __restrict__ w,
               __half* __restrict__ out)
{
    __shared__ float red[4];
    const int tok = blockIdx.x;
    const int t = threadIdx.x;
    const __half* row = kv + (size_t)tok * 576;
    float v[4];
    float s = 0.0f;
#pragma unroll
    for (int u = 0; u < 4; u++) {
        v[u] = __half2float(row[t + u * 128]);
        s = fmaf(v[u], v[u], s);
    }
#pragma unroll
    for (int off = 16; off > 0; off >>= 1)
        s += __shfl_down_sync(0xffffffffu, s, off);
    if ((t & 31) == 0) red[t >> 5] = s;
    __syncthreads();
    const float tot = red[0] + red[1] + red[2] + red[3];
    const float r = rsqrtf(tot * (1.0f / 512.0f) + 1e-6f);
    __half* orow = out + (size_t)tok * 512;
#pragma unroll
    for (int u = 0; u < 4; u++) {
        const int idx = t + u * 128;
        orow[idx] = __float2half_rn(v[u] * r * w[idx]);
    }
}

// ---------------------------------------------------------------------------
// RoPE (fp16 storage, fp32 math)
// ---------------------------------------------------------------------------
__global__ __launch_bounds__(512)
void rope_qh(__half* __restrict__ q)
{
    const int tok = blockIdx.x;
    const int h = threadIdx.x >> 5;
    const int i = threadIdx.x & 31;
    const int s = tok & (SEQ - 1);
    const float e = (float)(2 * i) * (1.0f / 64.0f);
    const float freq = 1.0f / powf(10000.0f, e);
    float sn, c;
    sincosf((float)s * freq, &sn, &c);
    __half2* p = (__half2*)(q + (size_t)tok * 2048 + h * 128 + 64) + i;
    const float2 v = __half22float2(*p);
    *p = __floats2half2_rn(v.x * c - v.y * sn, v.y * c + v.x * sn);
}

__global__ __launch_bounds__(32)
void rope_kh(const __half* __restrict__ kv, __half* __restrict__ kpe)
{
    const int tok = blockIdx.x;
    const int i = threadIdx.x;
    const int s = tok & (SEQ - 1);
    const float e = (float)(2 * i) * (1.0f / 64.0f);
    const float freq = 1.0f / powf(10000.0f, e);
    float sn, c;
    sincosf((float)s * freq, &sn, &c);
    const float x1 = __half2float(kv[(size_t)tok * 576 + 512 + 2 * i]);
    const float x2 = __half2float(kv[(size_t)tok * 576 + 512 + 2 * i + 1]);
    ((__half2*)(kpe + (size_t)tok * 64))[i] =
        __floats2half2_rn(x1 * c - x2 * sn, x2 * c + x1 * sn);
}

// ---------------------------------------------------------------------------
// Flash attention (causal, fp16 mma m16n8k16, fp32 softmax/accum).
// 128q x 64key tiles, d=128, 8 warps (wm 0..3: 32q band; wn 0..1).
// Q/K/V fp16 smem stride 136 halves; P fp16 stride 72; raw scores fp32.
// Scale folded into w_query. K = [kvdec nope | kpe]; V = kvdec[64..192).
// ---------------------------------------------------------------------------
#define F_QS 0
#define F_KS (F_QS + 128 * 136)     // 17408
#define F_VS (F_KS + 64 * 136)      // 26112
#define F_PS (F_VS + 64 * 136)      // 34816
#define F_PF (F_PS + 128 * 72)      // 44032 (halves); float region after
#define FLASH_SMEM (F_PF * 2 + (128 * 68 + 3 * 128) * 4)   // 124416 B

__global__ __launch_bounds__(256)
void flash_f16(const __half* __restrict__ qh, const __half* __restrict__ kvd,
               const __half* __restrict__ kpe, __half* __restrict__ o)
{
    extern __shared__ __half smh[];
    const uint32_t smb = (uint32_t)__cvta_generic_to_shared(smh);
    __half* Qs = smh + F_QS;
    __half* Ks = smh + F_KS;
    __half* Vs = smh + F_VS;
    __half* Ps = smh + F_PS;
    float*  Pf = (float*)(smh + F_PF);
    float*  rm = Pf + 128 * 68;
    float*  rl = rm + 128;
    float*  rf = rl + 128;

    const int t = threadIdx.x;
    const int lane = t & 31, wid = t >> 5;
    const int g = lane >> 2, tig = lane & 3;
    const int wm = wid >> 1;   // 0..3: 32-q band
    const int wn = wid & 1;    // 0..1
    const int qb = blockIdx.x, h = blockIdx.y, b = blockIdx.z;
    const int q0 = qb * 128;

    // stage Q (pre-scaled via w_query prep)
#pragma unroll
    for (int i = 0; i < 8; i++) {
        const int id = t + i * 256;
        const int r = id >> 4, c = (id & 15) * 8;
        *(uint4*)(Qs + r * 136 + c) =
            *(const uint4*)(qh + (size_t)(b * SEQ + q0 + r) * 2048 + h * 128 + c);
    }
    if (t < 128) { rm[t] = -1e30f; rl[t] = 0.f; }

    float oacc[2][8][4];
#pragma unroll
    for (int mt = 0; mt < 2; mt++)
#pragma unroll
        for (int nt = 0; nt < 8; nt++)
#pragma unroll
            for (int i = 0; i < 4; i++) oacc[mt][nt][i] = 0.f;

    // per-lane ldmatrix base offsets (halves)
    const int qBase = (wm * 32 + (lane & 15)) * 136 + (lane >> 4) * 8;   // A: Q
    const int kBase = (wn * 32 + (lane & 7)) * 136 + (lane >> 3) * 8;    // B: K (x4 non-trans)
    const int pBase = (wm * 32 + (lane & 15)) * 72 + (lane >> 4) * 8;    // A: P
    const int vBase = lane * 136 + wn * 64;                              // B: V (x4 trans)

    const int nkt = 2 * (qb + 1);
    for (int kt = 0; kt < nkt; kt++) {
        __syncthreads();
        const int k0 = kt * 64;
#pragma unroll
        for (int i = 0; i < 4; i++) {
            const int id = t + i * 256;
            const int r = id >> 4, c = (id & 15) * 8;
            const size_t tok = (size_t)(b * SEQ + k0 + r);
            const __half* ksrc = (c < 64) ? kvd + (tok * 16 + h) * 192 + c
                                          : kpe + tok * 64 + (c - 64);
            *(uint4*)(Ks + r * 136 + c) = *(const uint4*)ksrc;
            *(uint4*)(Vs + r * 136 + c) =
                *(const uint4*)(kvd + (tok * 16 + h) * 192 + 64 + c);
        }
        __syncthreads();

        // ---- scores: Q @ K^T ----
        float sacc[2][4][4];
#pragma unroll
        for (int mt = 0; mt < 2; mt++)
#pragma unroll
            for (int nt = 0; nt < 4; nt++)
#pragma unroll
                for (int i = 0; i < 4; i++) sacc[mt][nt][i] = 0.f;

#pragma unroll
        for (int dch = 0; dch < 4; dch++) {       // 32 d per chunk
            uint32_t kb[4][2][2];
#pragma unroll
            for (int nt = 0; nt < 4; nt++) {
                uint32_t rr[4];
                ldsm_x4(rr, smb + (uint32_t)(F_KS + kBase + nt * 8 * 136 + dch * 32) * 2);
                kb[nt][0][0] = rr[0]; kb[nt][0][1] = rr[1];
                kb[nt][1][0] = rr[2]; kb[nt][1][1] = rr[3];
            }
#pragma unroll
            for (int mt = 0; mt < 2; mt++) {
                uint32_t a0[4], a1[4];
                const uint32_t qa =
                    smb + (uint32_t)(F_QS + qBase + mt * 16 * 136 + dch * 32) * 2;
                ldsm_x4(a0, qa);
                ldsm_x4(a1, qa + 32);
#pragma unroll
                for (int nt = 0; nt < 4; nt++) {
                    mma_f16(sacc[mt][nt], a0, kb[nt][0]);
                    mma_f16(sacc[mt][nt], a1, kb[nt][1]);
                }
            }
        }

        // causal mask on last two tiles
        if (kt >= nkt - 2) {
#pragma unroll
            for (int mt = 0; mt < 2; mt++)
#pragma unroll
                for (int nt = 0; nt < 4; nt++) {
                    const int row = q0 + wm * 32 + mt * 16 + g;
                    const int col = k0 + wn * 32 + nt * 8 + 2 * tig;
                    if (col     > row)     sacc[mt][nt][0] = -1e30f;
                    if (col + 1 > row)     sacc[mt][nt][1] = -1e30f;
                    if (col     > row + 8) sacc[mt][nt][2] = -1e30f;
                    if (col + 1 > row + 8) sacc[mt][nt][3] = -1e30f;
                }
        }
#pragma unroll
        for (int mt = 0; mt < 2; mt++)
#pragma unroll
            for (int nt = 0; nt < 4; nt++) {
                const int lr = wm * 32 + mt * 16 + g;
                const int lc = wn * 32 + nt * 8 + 2 * tig;
                *(float2*)&Pf[lr * 68 + lc] =
                    make_float2(sacc[mt][nt][0], sacc[mt][nt][1]);
                *(float2*)&Pf[(lr + 8) * 68 + lc] =
                    make_float2(sacc[mt][nt][2], sacc[mt][nt][3]);
            }
        __syncthreads();

        // ---- online softmax: 2 threads/row; write fp16 P ----
        {
            const int row = t >> 1, hf = t & 1;
            float vals[32];
            const float* pr = Pf + row * 68 + hf * 32;
#pragma unroll
            for (int j = 0; j < 8; j++) {
                const float4 v4 = *(const float4*)(pr + j * 4);
                vals[j * 4 + 0] = v4.x; vals[j * 4 + 1] = v4.y;
                vals[j * 4 + 2] = v4.z; vals[j * 4 + 3] = v4.w;
            }
            const float mold = rm[row];
            float mx = mold;
#pragma unroll
            for (int c = 0; c < 32; c++) mx = fmaxf(mx, vals[c]);
            mx = fmaxf(mx, __shfl_xor_sync(0xffffffffu, mx, 1));
            const float f = __expf(mold - mx);
            float sum = 0.f;
            __half2* pw = (__half2*)(Ps + row * 72 + hf * 32);
#pragma unroll
            for (int j = 0; j < 16; j++) {
                const float p0 = __expf(vals[2 * j]     - mx);
                const float p1 = __expf(vals[2 * j + 1] - mx);
                sum += p0 + p1;
                pw[j] = __floats2half2_rn(p0, p1);
            }
            sum += __shfl_xor_sync(0xffffffffu, sum, 1);
            if (!hf) { rm[row] = mx; rl[row] = rl[row] * f + sum; rf[row] = f; }
        }
        __syncthreads();

        // ---- rescale accumulators, then O += P @ V ----
#pragma unroll
        for (int mt = 0; mt < 2; mt++) {
            const int rbase = wm * 32 + mt * 16;
            const float f0 = rf[rbase + g];
            const float f1 = rf[rbase + g + 8];
#pragma unroll
            for (int nt = 0; nt < 8; nt++) {
                oacc[mt][nt][0] *= f0; oacc[mt][nt][1] *= f0;
                oacc[mt][nt][2] *= f1; oacc[mt][nt][3] *= f1;
            }
        }
#pragma unroll
        for (int kch = 0; kch < 2; kch++) {      // keys 0-31, 32-63
            uint32_t vb[8][2][2];
#pragma unroll
            for (int nt = 0; nt < 8; nt++) {
                uint32_t rr[4];
                ldsm_x4_t(rr, smb + (uint32_t)(F_VS + vBase + kch * 32 * 136 + nt * 8) * 2);
                vb[nt][0][0] = rr[0]; vb[nt][0][1] = rr[1];
                vb[nt][1][0] = rr[2]; vb[nt][1][1] = rr[3];
            }
#pragma unroll
            for (int mt = 0; mt < 2; mt++) {
                uint32_t p0[4], p1[4];
                const uint32_t pa =
                    smb + (uint32_t)(F_PS + pBase + mt * 16 * 72 + kch * 32) * 2;
                ldsm_x4(p0, pa);
                ldsm_x4(p1, pa + 32);
#pragma unroll
                for (int nt = 0; nt < 8; nt++) {
                    mma_f16(oacc[mt][nt], p0, vb[nt][0]);
                    mma_f16(oacc[mt][nt], p1, vb[nt][1]);
                }
            }
        }
    }

    __syncthreads();
    // epilogue: divide by l, write fp16 attn
#pragma unroll
    for (int mt = 0; mt < 2; mt++) {
        const int rbase = wm * 32 + mt * 16;
        const float inv0 = 1.0f / rl[rbase + g];
        const float inv1 = 1.0f / rl[rbase + g + 8];
#pragma unroll
        for (int nt = 0; nt < 8; nt++) {
            const int col = wn * 64 + nt * 8 + 2 * tig;
            const size_t i0 = (size_t)(b * SEQ + q0 + rbase + g) * 2048 + h * 128 + col;
            const size_t i1 = (size_t)(b * SEQ + q0 + rbase + g + 8) * 2048 + h * 128 + col;
            *(__half2*)(o + i0) =
                __floats2half2_rn(oacc[mt][nt][0] * inv0, oacc[mt][nt][1] * inv0);
            *(__half2*)(o + i1) =
                __floats2half2_rn(oacc[mt][nt][2] * inv1, oacc[mt][nt][3] * inv1);
        }
    }
}

// ---------------------------------------------------------------------------
// Launch
// ---------------------------------------------------------------------------
extern "C" void kernel_launch(void* const* d_in, const int* in_sizes, int n_in,
                              void* d_out, int out_size)
{
    (void)in_sizes; (void)n_in; (void)out_size;
    const float* x          = (const float*)d_in[0];
    const float* w_query    = (const float*)d_in[1];
    const float* wkv_a      = (const float*)d_in[2];
    const float* wkv_b      = (const float*)d_in[3];
    const float* kv_norm_w  = (const float*)d_in[4];
    const float* out_proj_w = (const float*)d_in[5];
    float* out = (float*)d_out;

    __half *xh, *qh, *kvh, *kvch, *kpeh, *kvdech, *attnh, *wqh, *wkvah, *wkvbh, *wouth;
    cudaGetSymbolAddress((void**)&xh,     g_xh);
    cudaGetSymbolAddress((void**)&qh,     g_qh);
    cudaGetSymbolAddress((void**)&kvh,    g_kvh);
    cudaGetSymbolAddress((void**)&kvch,   g_kvch);
    cudaGetSymbolAddress((void**)&kpeh,   g_kpeh);
    cudaGetSymbolAddress((void**)&kvdech, g_kvdech);
    cudaGetSymbolAddress((void**)&attnh,  g_attnh);
    cudaGetSymbolAddress((void**)&wqh,    g_wqh);
    cudaGetSymbolAddress((void**)&wkvah,  g_wkvah);
    cudaGetSymbolAddress((void**)&wkvbh,  g_wkvbh);
    cudaGetSymbolAddress((void**)&wouth,  g_wouth);

    cudaFuncSetAttribute(gemm_f16<true>,
                         cudaFuncAttributeMaxDynamicSharedMemorySize, GEMM_SMEM);
    cudaFuncSetAttribute(gemm_f16<false>,
                         cudaFuncAttributeMaxDynamicSharedMemorySize, GEMM_SMEM);
    cudaFuncSetAttribute(flash_f16,
                         cudaFuncAttributeMaxDynamicSharedMemorySize, FLASH_SMEM);

    const float qscale = 0.08838834764831845f;  // 1/sqrt(128), folded into w_query

    // --- fp16 prep casts ---
    prep_half<<<(TOKS * 2048 / 4 + 255) / 256, 256>>>(x, xh, 1.0f, TOKS * 2048 / 4);
    prep_half<<<(2048 * 2048 / 4 + 255) / 256, 256>>>(w_query, wqh, qscale, 2048 * 2048 / 4);
    prep_half<<<(2048 * 576 / 4 + 255) / 256, 256>>>(wkv_a, wkvah, 1.0f, 2048 * 576 / 4);
    prep_half<<<(512 * 3072 / 4 + 255) / 256, 256>>>(wkv_b, wkvbh, 1.0f, 512 * 3072 / 4);
    prep_half<<<(2048 * 2048 / 4 + 255) / 256, 256>>>(out_proj_w, wouth, 1.0f, 2048 * 2048 / 4);

    // q = x @ (w_query * scale)   [4096,2048] fp16
    gemm_f16<true><<<dim3(16, 32), 256, GEMM_SMEM>>>(xh, wqh, qh, TOKS, 2048, 2048);
    // kv = x @ wkv_a              [4096,576] fp16
    gemm_f16<true><<<dim3(5, 32), 256, GEMM_SMEM>>>(xh, wkvah, kvh, TOKS, 576, 2048);
    // rope q_pe in place (fp16)
    rope_qh<<<TOKS, 512>>>(qh);
    // rmsnorm latent -> kvch fp16
    rmsnorm_h<<<TOKS, 128>>>(kvh, kv_norm_w, kvch);
    // rope k_pe -> kpeh fp16
    rope_kh<<<TOKS, 32>>>(kvh, kpeh);
    // kv_dec = kvc @ wkv_b        [4096,3072] fp16
    gemm_f16<true><<<dim3(24, 32), 256, GEMM_SMEM>>>(kvch, wkvbh, kvdech, TOKS, 3072, 512);
    // causal flash attention -> attnh fp16
    flash_f16<<<dim3(SEQ / 128, 16, 2), 256, FLASH_SMEM>>>(qh, kvdech, kpeh, attnh);
    // out = attn @ out_proj_w     [4096,2048] fp32
    gemm_f16<false><<<dim3(16, 32), 256, GEMM_SMEM>>>(attnh, wouth, out, TOKS, 2048, 2048);
}

// round 10
// speedup vs baseline: 3.0984x; 1.1115x over previous
#include <cuda_runtime.h>
#include <cuda_fp16.h>
#include <math.h>
#include <stdint.h>

// B=2, S=2048, T=4096, D_IN=2048, H=16, QK_HEAD=128, V_HEAD=128, KV_RANK=512
#define TOKS 4096
#define SEQ  2048

// ---------------------------------------------------------------------------
// Scratch (fp16)
// ---------------------------------------------------------------------------
__device__ __half g_xh[(size_t)TOKS * 2048];
__device__ __half g_qh[(size_t)TOKS * 2048];
__device__ __half g_kvh[(size_t)TOKS * 576];
__device__ __half g_kvch[(size_t)TOKS * 512];
__device__ __half g_kpeh[(size_t)TOKS * 64];
__device__ __half g_kvdech[(size_t)TOKS * 3072];
__device__ __half g_attnh[(size_t)TOKS * 2048];
__device__ __half g_wqh[(size_t)2048 * 2048];
__device__ __half g_wkvah[(size_t)2048 * 576];
__device__ __half g_wkvbh[(size_t)512 * 3072];
__device__ __half g_wouth[(size_t)2048 * 2048];

// ---------------------------------------------------------------------------
// Helpers
// ---------------------------------------------------------------------------
__device__ __forceinline__ uint32_t h2_to_u32(__half2 h) {
    union { __half2 h2; uint32_t u; } cvt;
    cvt.h2 = h;
    return cvt.u;
}

__device__ __forceinline__ void mma_f16(float* d, const uint32_t* a, const uint32_t* b) {
    asm volatile(
        "mma.sync.aligned.m16n8k16.row.col.f32.f16.f16.f32 "
        "{%0,%1,%2,%3}, {%4,%5,%6,%7}, {%8,%9}, {%0,%1,%2,%3};\n"
        : "+f"(d[0]), "+f"(d[1]), "+f"(d[2]), "+f"(d[3])
        : "r"(a[0]), "r"(a[1]), "r"(a[2]), "r"(a[3]), "r"(b[0]), "r"(b[1]));
}
__device__ __forceinline__ void ldsm_x4(uint32_t* r, uint32_t addr) {
    asm volatile("ldmatrix.sync.aligned.m8n8.x4.shared.b16 {%0,%1,%2,%3}, [%4];\n"
                 : "=r"(r[0]), "=r"(r[1]), "=r"(r[2]), "=r"(r[3]) : "r"(addr));
}
__device__ __forceinline__ void ldsm_x4_t(uint32_t* r, uint32_t addr) {
    asm volatile("ldmatrix.sync.aligned.m8n8.x4.trans.shared.b16 {%0,%1,%2,%3}, [%4];\n"
                 : "=r"(r[0]), "=r"(r[1]), "=r"(r[2]), "=r"(r[3]) : "r"(addr));
}
__device__ __forceinline__ void cp_async16(void* smem_ptr, const void* gptr) {
    uint32_t saddr = (uint32_t)__cvta_generic_to_shared(smem_ptr);
    asm volatile("cp.async.cg.shared.global [%0], [%1], 16;\n"
                 :: "r"(saddr), "l"(gptr) : "memory");
}
__device__ __forceinline__ void cp_async16z(void* smem_ptr, const void* gptr, int sz) {
    uint32_t saddr = (uint32_t)__cvta_generic_to_shared(smem_ptr);
    asm volatile("cp.async.cg.shared.global [%0], [%1], 16, %2;\n"
                 :: "r"(saddr), "l"(gptr), "r"(sz) : "memory");
}
__device__ __forceinline__ void cp_commit() {
    asm volatile("cp.async.commit_group;\n" ::: "memory");
}
template <int N>
__device__ __forceinline__ void cp_wait() {
    asm volatile("cp.async.wait_group %0;\n" :: "n"(N) : "memory");
}

// ---------------------------------------------------------------------------
// Pre-pass: fp32 -> fp16 elementwise (optional scale)
// ---------------------------------------------------------------------------
__global__ __launch_bounds__(256)
void prep_half(const float* __restrict__ in, __half* __restrict__ out,
               float scale, int n4)
{
    const int i = blockIdx.x * 256 + threadIdx.x;
    if (i >= n4) return;
    const float4 v = ((const float4*)in)[i];
    __half2* o = (__half2*)out + (size_t)i * 2;
    o[0] = __floats2half2_rn(v.x * scale, v.y * scale);
    o[1] = __floats2half2_rn(v.z * scale, v.w * scale);
}

// ---------------------------------------------------------------------------
// FP16 GEMM (unchanged from R7): C[M,N] = A[M,K] @ B[K,N].
// ---------------------------------------------------------------------------
#define GA_STR 40
#define GB_STR 136
#define GA_H (128 * GA_STR)
#define GB_H (32 * GB_STR)
#define GEMM_SMEM ((2 * GA_H + 2 * GB_H) * 2)

template <bool HALF_OUT>
__global__ __launch_bounds__(256)
void gemm_f16(const __half* __restrict__ A, const __half* __restrict__ B,
              void* __restrict__ Cv, int M, int N, int K)
{
    extern __shared__ __half smh[];
    const uint32_t smb = (uint32_t)__cvta_generic_to_shared(smh);

    const int t = threadIdx.x;
    const int lane = t & 31, wid = t >> 5;
    const int g = lane >> 2, tig = lane & 3;
    const int wm = wid >> 2;
    const int wn = wid & 3;
    const int row0 = blockIdx.y * 128;
    const int col0 = blockIdx.x * 128;

    float acc[4][4][4];
#pragma unroll
    for (int mt = 0; mt < 4; mt++)
#pragma unroll
        for (int nt = 0; nt < 4; nt++)
#pragma unroll
            for (int i = 0; i < 4; i++) acc[mt][nt][i] = 0.f;

    const int nkt = K >> 5;

#define G_STAGE(buf, k0)                                                       \
    {                                                                          \
        __half* As = smh + (buf) * GA_H;                                       \
        __half* Bs = smh + 2 * GA_H + (buf) * GB_H;                            \
        _Pragma("unroll")                                                      \
        for (int i = 0; i < 2; i++) {                                          \
            const int id = t + i * 256;                                        \
            const int ar = id >> 2, ac = (id & 3) * 8;                         \
            cp_async16z(As + ar * GA_STR + ac,                                 \
                        A + (size_t)(row0 + ar) * K + (k0) + ac, 16);          \
            const int kr = id >> 4, nc = (id & 15) * 8;                        \
            const int col = col0 + nc;                                         \
            const int sz = (col + 8 <= N) ? 16 : 0;                            \
            cp_async16z(Bs + kr * GB_STR + nc,                                 \
                        B + (size_t)((k0) + kr) * N + (sz ? col : 0), sz);     \
        }                                                                      \
    }

    G_STAGE(0, 0);
    cp_commit();

    for (int kt = 0; kt < nkt; kt++) {
        if (kt + 1 < nkt) {
            G_STAGE((kt + 1) & 1, (kt + 1) << 5);
            cp_commit();
            cp_wait<1>();
        } else {
            cp_wait<0>();
        }
        __syncthreads();

        const uint32_t asb = smb + ((kt & 1) * GA_H) * 2;
        const uint32_t bsb = smb + (2 * GA_H + (kt & 1) * GB_H) * 2;

        uint32_t bf[4][2][2];
        const uint32_t baddr = bsb + ((uint32_t)(lane * GB_STR + wn * 32)) * 2;
#pragma unroll
        for (int nt = 0; nt < 4; nt++) {
            uint32_t rr[4];
            ldsm_x4_t(rr, baddr + nt * 16);
            bf[nt][0][0] = rr[0]; bf[nt][0][1] = rr[1];
            bf[nt][1][0] = rr[2]; bf[nt][1][1] = rr[3];
        }
        const uint32_t aaddr =
            asb + ((uint32_t)((wm * 64 + (lane & 15)) * GA_STR + (lane >> 4) * 8)) * 2;
#pragma unroll
        for (int mt = 0; mt < 4; mt++) {
            uint32_t a0[4], a1[4];
            ldsm_x4(a0, aaddr + mt * (16 * GA_STR * 2));
            ldsm_x4(a1, aaddr + mt * (16 * GA_STR * 2) + 32);
#pragma unroll
            for (int nt = 0; nt < 4; nt++) {
                mma_f16(acc[mt][nt], a0, bf[nt][0]);
                mma_f16(acc[mt][nt], a1, bf[nt][1]);
            }
        }
        __syncthreads();
    }

#pragma unroll
    for (int mt = 0; mt < 4; mt++) {
        const int gr0 = row0 + wm * 64 + mt * 16 + g;
#pragma unroll
        for (int nt = 0; nt < 4; nt++) {
            const int gc = col0 + wn * 32 + nt * 8 + 2 * tig;
            if (gc < N) {
                if (HALF_OUT) {
                    __half* C = (__half*)Cv;
                    *(__half2*)(C + (size_t)gr0 * N + gc) =
                        __floats2half2_rn(acc[mt][nt][0], acc[mt][nt][1]);
                    *(__half2*)(C + (size_t)(gr0 + 8) * N + gc) =
                        __floats2half2_rn(acc[mt][nt][2], acc[mt][nt][3]);
                } else {
                    float* C = (float*)Cv;
                    *(float2*)(C + (size_t)gr0 * N + gc) =
                        make_float2(acc[mt][nt][0], acc[mt][nt][1]);
                    *(float2*)(C + (size_t)(gr0 + 8) * N + gc) =
                        make_float2(acc[mt][nt][2], acc[mt][nt][3]);
                }
            }
        }
    }
}

// ---------------------------------------------------------------------------
// RMSNorm / RoPE (unchanged)
// ---------------------------------------------------------------------------
__global__ __launch_bounds__(128)
void rmsnorm_h(const __half* __restrict__ kv, const float* __restrict__ w,
               __half* __restrict__ out)
{
    __shared__ float red[4];
    const int tok = blockIdx.x;
    const int t = threadIdx.x;
    const __half* row = kv + (size_t)tok * 576;
    float v[4];
    float s = 0.0f;
#pragma unroll
    for (int u = 0; u < 4; u++) {
        v[u] = __half2float(row[t + u * 128]);
        s = fmaf(v[u], v[u], s);
    }
#pragma unroll
    for (int off = 16; off > 0; off >>= 1)
        s += __shfl_down_sync(0xffffffffu, s, off);
    if ((t & 31) == 0) red[t >> 5] = s;
    __syncthreads();
    const float tot = red[0] + red[1] + red[2] + red[3];
    const float r = rsqrtf(tot * (1.0f / 512.0f) + 1e-6f);
    __half* orow = out + (size_t)tok * 512;
#pragma unroll
    for (int u = 0; u < 4; u++) {
        const int idx = t + u * 128;
        orow[idx] = __float2half_rn(v[u] * r * w[idx]);
    }
}

__global__ __launch_bounds__(512)
void rope_qh(__half* __restrict__ q)
{
    const int tok = blockIdx.x;
    const int h = threadIdx.x >> 5;
    const int i = threadIdx.x & 31;
    const int s = tok & (SEQ - 1);
    const float e = (float)(2 * i) * (1.0f / 64.0f);
    const float freq = 1.0f / powf(10000.0f, e);
    float sn, c;
    sincosf((float)s * freq, &sn, &c);
    __half2* p = (__half2*)(q + (size_t)tok * 2048 + h * 128 + 64) + i;
    const float2 v = __half22float2(*p);
    *p = __floats2half2_rn(v.x * c - v.y * sn, v.y * c + v.x * sn);
}

__global__ __launch_bounds__(32)
void rope_kh(const __half* __restrict__ kv, __half* __restrict__ kpe)
{
    const int tok = blockIdx.x;
    const int i = threadIdx.x;
    const int s = tok & (SEQ - 1);
    const float e = (float)(2 * i) * (1.0f / 64.0f);
    const float freq = 1.0f / powf(10000.0f, e);
    float sn, c;
    sincosf((float)s * freq, &sn, &c);
    const float x1 = __half2float(kv[(size_t)tok * 576 + 512 + 2 * i]);
    const float x2 = __half2float(kv[(size_t)tok * 576 + 512 + 2 * i + 1]);
    ((__half2*)(kpe + (size_t)tok * 64))[i] =
        __floats2half2_rn(x1 * c - x2 * sn, x2 * c + x1 * sn);
}

// ---------------------------------------------------------------------------
// Flash attention v3 (FA2-style): 128q x 64key tiles, d=128, 8 warps.
// Warp w owns q rows [w*16, w*16+16) across ALL keys: P stays in registers
// (QK C-frag == PV A-frag). Softmax in registers (exp2, log2e pre-folded
// into w_query). K/V cp.async double-buffered. One __syncthreads per tile.
// smem (halves): Q[128*136] | K0,K1[64*136] | V0,V1[64*136]
// ---------------------------------------------------------------------------
#define FV_Q  0
#define FV_K0 17408
#define FV_K1 26112
#define FV_V0 34816
#define FV_V1 43520
#define FLASH_SMEM (52224 * 2)

__global__ __launch_bounds__(256)
void flash_v3(const __half* __restrict__ qh, const __half* __restrict__ kvd,
              const __half* __restrict__ kpe, __half* __restrict__ o)
{
    extern __shared__ __half smh[];
    const uint32_t smb = (uint32_t)__cvta_generic_to_shared(smh);

    const int t = threadIdx.x;
    const int lane = t & 31, w = t >> 5;
    const int g = lane >> 2, tig = lane & 3;
    const int qb = blockIdx.x, h = blockIdx.y, b = blockIdx.z;
    const int q0 = qb * 128;

    // stage Q tile (plain vector loads; once per block)
#pragma unroll
    for (int i = 0; i < 8; i++) {
        const int id = t + i * 256;
        const int r = id >> 4, c = (id & 15) * 8;
        *(uint4*)(smh + FV_Q + r * 136 + c) =
            *(const uint4*)(qh + (size_t)(b * SEQ + q0 + r) * 2048 + h * 128 + c);
    }

    // K/V staging: 16 chunks per row (K: 8 nope + 8 rope; V: 8..16 of kvrow)
#define FV_STAGE(koff, voff, ktile)                                            \
    {                                                                          \
        const int k0_ = (ktile) * 64;                                          \
        _Pragma("unroll")                                                      \
        for (int i = 0; i < 4; i++) {                                          \
            const int id = t + i * 256;                                        \
            const int r = id >> 4, c8 = id & 15;                               \
            const size_t tok = (size_t)(b * SEQ + k0_ + r);                    \
            const __half* ks = (c8 < 8)                                        \
                ? kvd + (tok * 16 + h) * 192 + c8 * 8                          \
                : kpe + tok * 64 + (c8 - 8) * 8;                               \
            cp_async16(smh + (koff) + r * 136 + c8 * 8, ks);                   \
            cp_async16(smh + (voff) + r * 136 + c8 * 8,                        \
                       kvd + (tok * 16 + h) * 192 + 64 + c8 * 8);              \
        }                                                                      \
    }

    FV_STAGE(FV_K0, FV_V0, 0);
    cp_commit();

    float oacc[16][4];
#pragma unroll
    for (int nt = 0; nt < 16; nt++)
#pragma unroll
        for (int i = 0; i < 4; i++) oacc[nt][i] = 0.f;

    float m0 = -1e30f, m1 = -1e30f, l0 = 0.f, l1 = 0.f;

    const uint32_t qByte =
        smb + (uint32_t)((FV_Q + (w * 16 + (lane & 15)) * 136 + (lane >> 4) * 8)) * 2;
    const uint32_t kRow = (uint32_t)((lane & 7) * 136 + (lane >> 3) * 8) * 2;
    const uint32_t vRow = (uint32_t)(lane * 136) * 2;

    const int nkt = 2 * (qb + 1);
    for (int kt = 0; kt < nkt; kt++) {
        cp_wait<0>();
        __syncthreads();
        const int bsel = kt & 1;
        if (kt + 1 < nkt) {
            if (bsel) { FV_STAGE(FV_K0, FV_V0, kt + 1); }
            else      { FV_STAGE(FV_K1, FV_V1, kt + 1); }
            cp_commit();
        }
        const uint32_t kBase = smb + (bsel ? FV_K1 : FV_K0) * 2 + kRow;
        const uint32_t vBase = smb + (bsel ? FV_V1 : FV_V0) * 2 + vRow;
        const int k0 = kt * 64;

        // ---- scores: sacc[nt] = Q(16 rows) @ K(nt octet)^T ----
        float sacc[8][4];
#pragma unroll
        for (int nt = 0; nt < 8; nt++)
#pragma unroll
            for (int i = 0; i < 4; i++) sacc[nt][i] = 0.f;

#pragma unroll
        for (int dch = 0; dch < 4; dch++) {
            uint32_t a0[4], a1[4];
            ldsm_x4(a0, qByte + dch * 64);
            ldsm_x4(a1, qByte + dch * 64 + 32);
#pragma unroll
            for (int ng = 0; ng < 2; ng++) {
                uint32_t kb[4][2][2];
#pragma unroll
                for (int j = 0; j < 4; j++) {
                    uint32_t rr[4];
                    ldsm_x4(rr, kBase + (ng * 4 + j) * (8 * 136 * 2) + dch * 64);
                    kb[j][0][0] = rr[0]; kb[j][0][1] = rr[1];
                    kb[j][1][0] = rr[2]; kb[j][1][1] = rr[3];
                }
#pragma unroll
                for (int j = 0; j < 4; j++) {
                    mma_f16(sacc[ng * 4 + j], a0, kb[j][0]);
                    mma_f16(sacc[ng * 4 + j], a1, kb[j][1]);
                }
            }
        }

        // causal mask (two diagonal-adjacent tiles)
        if (kt >= nkt - 2) {
            const int row0 = q0 + w * 16 + g;
#pragma unroll
            for (int nt = 0; nt < 8; nt++) {
                const int col = k0 + nt * 8 + 2 * tig;
                if (col     > row0)     sacc[nt][0] = -1e30f;
                if (col + 1 > row0)     sacc[nt][1] = -1e30f;
                if (col     > row0 + 8) sacc[nt][2] = -1e30f;
                if (col + 1 > row0 + 8) sacc[nt][3] = -1e30f;
            }
        }

        // ---- register softmax (base-2; log2e folded into q scale) ----
        float mx0 = m0, mx1 = m1;
#pragma unroll
        for (int nt = 0; nt < 8; nt++) {
            mx0 = fmaxf(mx0, fmaxf(sacc[nt][0], sacc[nt][1]));
            mx1 = fmaxf(mx1, fmaxf(sacc[nt][2], sacc[nt][3]));
        }
        mx0 = fmaxf(mx0, __shfl_xor_sync(0xffffffffu, mx0, 1));
        mx0 = fmaxf(mx0, __shfl_xor_sync(0xffffffffu, mx0, 2));
        mx1 = fmaxf(mx1, __shfl_xor_sync(0xffffffffu, mx1, 1));
        mx1 = fmaxf(mx1, __shfl_xor_sync(0xffffffffu, mx1, 2));
        const float f0 = exp2f(m0 - mx0);
        const float f1 = exp2f(m1 - mx1);
        float s0 = 0.f, s1 = 0.f;
        uint32_t ph[8][2];
#pragma unroll
        for (int nt = 0; nt < 8; nt++) {
            const float p00 = exp2f(sacc[nt][0] - mx0);
            const float p01 = exp2f(sacc[nt][1] - mx0);
            const float p10 = exp2f(sacc[nt][2] - mx1);
            const float p11 = exp2f(sacc[nt][3] - mx1);
            s0 += p00 + p01;
            s1 += p10 + p11;
            ph[nt][0] = h2_to_u32(__floats2half2_rn(p00, p01));
            ph[nt][1] = h2_to_u32(__floats2half2_rn(p10, p11));
        }
        s0 += __shfl_xor_sync(0xffffffffu, s0, 1);
        s0 += __shfl_xor_sync(0xffffffffu, s0, 2);
        s1 += __shfl_xor_sync(0xffffffffu, s1, 1);
        s1 += __shfl_xor_sync(0xffffffffu, s1, 2);
        l0 = l0 * f0 + s0;
        l1 = l1 * f1 + s1;
        m0 = mx0;
        m1 = mx1;
#pragma unroll
        for (int nt = 0; nt < 16; nt++) {
            oacc[nt][0] *= f0; oacc[nt][1] *= f0;
            oacc[nt][2] *= f1; oacc[nt][3] *= f1;
        }

        // ---- O += P @ V (P from registers) ----
#pragma unroll
        for (int vch = 0; vch < 2; vch++) {
            const uint32_t A0[4] = {ph[4 * vch + 0][0], ph[4 * vch + 0][1],
                                    ph[4 * vch + 1][0], ph[4 * vch + 1][1]};
            const uint32_t A1[4] = {ph[4 * vch + 2][0], ph[4 * vch + 2][1],
                                    ph[4 * vch + 3][0], ph[4 * vch + 3][1]};
#pragma unroll
            for (int ng = 0; ng < 4; ng++) {
                uint32_t vb[4][2][2];
#pragma unroll
                for (int j = 0; j < 4; j++) {
                    uint32_t rr[4];
                    ldsm_x4_t(rr, vBase + vch * (32 * 136 * 2) + (ng * 4 + j) * 16);
                    vb[j][0][0] = rr[0]; vb[j][0][1] = rr[1];
                    vb[j][1][0] = rr[2]; vb[j][1][1] = rr[3];
                }
#pragma unroll
                for (int j = 0; j < 4; j++) {
                    mma_f16(oacc[ng * 4 + j], A0, vb[j][0]);
                    mma_f16(oacc[ng * 4 + j], A1, vb[j][1]);
                }
            }
        }
    }

    // epilogue
    const float inv0 = 1.0f / l0;
    const float inv1 = 1.0f / l1;
    const size_t r0 = (size_t)(b * SEQ + q0 + w * 16 + g) * 2048 + h * 128;
    const size_t r1 = (size_t)(b * SEQ + q0 + w * 16 + g + 8) * 2048 + h * 128;
#pragma unroll
    for (int nt = 0; nt < 16; nt++) {
        const int col = nt * 8 + 2 * tig;
        *(__half2*)(o + r0 + col) =
            __floats2half2_rn(oacc[nt][0] * inv0, oacc[nt][1] * inv0);
        *(__half2*)(o + r1 + col) =
            __floats2half2_rn(oacc[nt][2] * inv1, oacc[nt][3] * inv1);
    }
}

// ---------------------------------------------------------------------------
// Launch
// ---------------------------------------------------------------------------
extern "C" void kernel_launch(void* const* d_in, const int* in_sizes, int n_in,
                              void* d_out, int out_size)
{
    (void)in_sizes; (void)n_in; (void)out_size;
    const float* x          = (const float*)d_in[0];
    const float* w_query    = (const float*)d_in[1];
    const float* wkv_a      = (const float*)d_in[2];
    const float* wkv_b      = (const float*)d_in[3];
    const float* kv_norm_w  = (const float*)d_in[4];
    const float* out_proj_w = (const float*)d_in[5];
    float* out = (float*)d_out;

    __half *xh, *qh, *kvh, *kvch, *kpeh, *kvdech, *attnh, *wqh, *wkvah, *wkvbh, *wouth;
    cudaGetSymbolAddress((void**)&xh,     g_xh);
    cudaGetSymbolAddress((void**)&qh,     g_qh);
    cudaGetSymbolAddress((void**)&kvh,    g_kvh);
    cudaGetSymbolAddress((void**)&kvch,   g_kvch);
    cudaGetSymbolAddress((void**)&kpeh,   g_kpeh);
    cudaGetSymbolAddress((void**)&kvdech, g_kvdech);
    cudaGetSymbolAddress((void**)&attnh,  g_attnh);
    cudaGetSymbolAddress((void**)&wqh,    g_wqh);
    cudaGetSymbolAddress((void**)&wkvah,  g_wkvah);
    cudaGetSymbolAddress((void**)&wkvbh,  g_wkvbh);
    cudaGetSymbolAddress((void**)&wouth,  g_wouth);

    cudaFuncSetAttribute(gemm_f16<true>,
                         cudaFuncAttributeMaxDynamicSharedMemorySize, GEMM_SMEM);
    cudaFuncSetAttribute(gemm_f16<false>,
                         cudaFuncAttributeMaxDynamicSharedMemorySize, GEMM_SMEM);
    cudaFuncSetAttribute(flash_v3,
                         cudaFuncAttributeMaxDynamicSharedMemorySize, FLASH_SMEM);

    // 1/sqrt(128) * log2(e): flash softmax runs in base-2 domain
    const float qscale = 0.08838834764831845f * 1.44269504088896340736f;

    prep_half<<<(TOKS * 2048 / 4 + 255) / 256, 256>>>(x, xh, 1.0f, TOKS * 2048 / 4);
    prep_half<<<(2048 * 2048 / 4 + 255) / 256, 256>>>(w_query, wqh, qscale, 2048 * 2048 / 4);
    prep_half<<<(2048 * 576 / 4 + 255) / 256, 256>>>(wkv_a, wkvah, 1.0f, 2048 * 576 / 4);
    prep_half<<<(512 * 3072 / 4 + 255) / 256, 256>>>(wkv_b, wkvbh, 1.0f, 512 * 3072 / 4);
    prep_half<<<(2048 * 2048 / 4 + 255) / 256, 256>>>(out_proj_w, wouth, 1.0f, 2048 * 2048 / 4);

    // q = x @ (w_query * qscale)  [4096,2048] fp16
    gemm_f16<true><<<dim3(16, 32), 256, GEMM_SMEM>>>(xh, wqh, qh, TOKS, 2048, 2048);
    // kv = x @ wkv_a              [4096,576] fp16
    gemm_f16<true><<<dim3(5, 32), 256, GEMM_SMEM>>>(xh, wkvah, kvh, TOKS, 576, 2048);
    // rope q_pe in place
    rope_qh<<<TOKS, 512>>>(qh);
    // rmsnorm latent
    rmsnorm_h<<<TOKS, 128>>>(kvh, kv_norm_w, kvch);
    // rope k_pe
    rope_kh<<<TOKS, 32>>>(kvh, kpeh);
    // kv_dec = kvc @ wkv_b        [4096,3072] fp16
    gemm_f16<true><<<dim3(24, 32), 256, GEMM_SMEM>>>(kvch, wkvbh, kvdech, TOKS, 3072, 512);
    // causal flash attention (register-resident P, cp.async K/V)
    flash_v3<<<dim3(SEQ / 128, 16, 2), 256, FLASH_SMEM>>>(qh, kvdech, kpeh, attnh);
    // out = attn @ out_proj_w     [4096,2048] fp32
    gemm_f16<false><<<dim3(16, 32), 256, GEMM_SMEM>>>(attnh, wouth, out, TOKS, 2048, 2048);
}

// round 11
// speedup vs baseline: 3.1504x; 1.0168x over previous
#include <cuda_runtime.h>
#include <cuda_fp16.h>
#include <math.h>
#include <stdint.h>

// B=2, S=2048, T=4096, D_IN=2048, H=16, QK_HEAD=128, V_HEAD=128, KV_RANK=512
#define TOKS 4096
#define SEQ  2048

// ---------------------------------------------------------------------------
// Scratch (fp16)
// ---------------------------------------------------------------------------
__device__ __half g_xh[(size_t)TOKS * 2048];
__device__ __half g_qh[(size_t)TOKS * 2048];
__device__ __half g_kvh[(size_t)TOKS * 576];
__device__ __half g_kvch[(size_t)TOKS * 512];
__device__ __half g_kpeh[(size_t)TOKS * 64];
__device__ __half g_kvdech[(size_t)TOKS * 3072];
__device__ __half g_attnh[(size_t)TOKS * 2048];
__device__ __half g_wqh[(size_t)2048 * 2048];
__device__ __half g_wkvah[(size_t)2048 * 576];
__device__ __half g_wkvbh[(size_t)512 * 3072];
__device__ __half g_wouth[(size_t)2048 * 2048];

// ---------------------------------------------------------------------------
// Helpers
// ---------------------------------------------------------------------------
__device__ __forceinline__ uint32_t h2_to_u32(__half2 h) {
    union { __half2 h2; uint32_t u; } cvt;
    cvt.h2 = h;
    return cvt.u;
}

__device__ __forceinline__ void mma_f16(float* d, const uint32_t* a, const uint32_t* b) {
    asm volatile(
        "mma.sync.aligned.m16n8k16.row.col.f32.f16.f16.f32 "
        "{%0,%1,%2,%3}, {%4,%5,%6,%7}, {%8,%9}, {%0,%1,%2,%3};\n"
        : "+f"(d[0]), "+f"(d[1]), "+f"(d[2]), "+f"(d[3])
        : "r"(a[0]), "r"(a[1]), "r"(a[2]), "r"(a[3]), "r"(b[0]), "r"(b[1]));
}
__device__ __forceinline__ void ldsm_x4(uint32_t* r, uint32_t addr) {
    asm volatile("ldmatrix.sync.aligned.m8n8.x4.shared.b16 {%0,%1,%2,%3}, [%4];\n"
                 : "=r"(r[0]), "=r"(r[1]), "=r"(r[2]), "=r"(r[3]) : "r"(addr));
}
__device__ __forceinline__ void ldsm_x4_t(uint32_t* r, uint32_t addr) {
    asm volatile("ldmatrix.sync.aligned.m8n8.x4.trans.shared.b16 {%0,%1,%2,%3}, [%4];\n"
                 : "=r"(r[0]), "=r"(r[1]), "=r"(r[2]), "=r"(r[3]) : "r"(addr));
}
__device__ __forceinline__ void cp_async16(void* smem_ptr, const void* gptr) {
    uint32_t saddr = (uint32_t)__cvta_generic_to_shared(smem_ptr);
    asm volatile("cp.async.cg.shared.global [%0], [%1], 16;\n"
                 :: "r"(saddr), "l"(gptr) : "memory");
}
__device__ __forceinline__ void cp_async16z(void* smem_ptr, const void* gptr, int sz) {
    uint32_t saddr = (uint32_t)__cvta_generic_to_shared(smem_ptr);
    asm volatile("cp.async.cg.shared.global [%0], [%1], 16, %2;\n"
                 :: "r"(saddr), "l"(gptr), "r"(sz) : "memory");
}
__device__ __forceinline__ void cp_commit() {
    asm volatile("cp.async.commit_group;\n" ::: "memory");
}
template <int N>
__device__ __forceinline__ void cp_wait() {
    asm volatile("cp.async.wait_group %0;\n" :: "n"(N) : "memory");
}

// ---------------------------------------------------------------------------
// Pre-pass: fp32 -> fp16 elementwise (optional scale)
// ---------------------------------------------------------------------------
__global__ __launch_bounds__(256)
void prep_half(const float* __restrict__ in, __half* __restrict__ out,
               float scale, int n4)
{
    const int i = blockIdx.x * 256 + threadIdx.x;
    if (i >= n4) return;
    const float4 v = ((const float4*)in)[i];
    __half2* o = (__half2*)out + (size_t)i * 2;
    o[0] = __floats2half2_rn(v.x * scale, v.y * scale);
    o[1] = __floats2half2_rn(v.z * scale, v.w * scale);
}

// ---------------------------------------------------------------------------
// FP16 GEMM v2: C[M,N] = A[M,K] @ B[K,N].
// BM=BN=128, BK=64, 256 thr / 8 warps (warp tile 64x32), 2 CTAs/SM pinned.
// 3-stage cp.async pipeline, ONE __syncthreads per K-iteration.
// A smem [128][72] halves (144B rows), B smem [64][136] halves (272B rows);
// both strides give conflict-free ldmatrix phases.
// Requires M%128==0, K%64==0; N tail guarded (zfill).
// ---------------------------------------------------------------------------
#define G2_ASTR 72
#define G2_BSTR 136
#define G2_AH (128 * G2_ASTR)            // 9216 halves
#define G2_BH (64 * G2_BSTR)             // 8704 halves
#define G2_STG (G2_AH + G2_BH)           // 17920 halves / stage
#define GEMM_SMEM (3 * G2_STG * 2)       // 107520 B

template <bool HALF_OUT>
__global__ __launch_bounds__(256, 2)
void gemm_f16(const __half* __restrict__ A, const __half* __restrict__ B,
              void* __restrict__ Cv, int M, int N, int K)
{
    extern __shared__ __half smh[];
    const uint32_t smb = (uint32_t)__cvta_generic_to_shared(smh);

    const int t = threadIdx.x;
    const int lane = t & 31, wid = t >> 5;
    const int g = lane >> 2, tig = lane & 3;
    const int wm = wid >> 2;      // 0..1 -> 64 rows
    const int wn = wid & 3;       // 0..3 -> 32 cols
    const int row0 = blockIdx.y * 128;
    const int col0 = blockIdx.x * 128;

    float acc[4][4][4];
#pragma unroll
    for (int mt = 0; mt < 4; mt++)
#pragma unroll
        for (int nt = 0; nt < 4; nt++)
#pragma unroll
            for (int i = 0; i < 4; i++) acc[mt][nt][i] = 0.f;

    const int nkt = K >> 6;   // BK = 64; nkt >= 2 for all our shapes

#define G2_STAGE(buf, k0)                                                      \
    {                                                                          \
        __half* As = smh + (buf) * G2_STG;                                     \
        __half* Bs = As + G2_AH;                                               \
        _Pragma("unroll")                                                      \
        for (int i = 0; i < 4; i++) {                                          \
            const int id = t + i * 256;                                        \
            const int ar = id >> 3, ac = (id & 7) * 8;                         \
            cp_async16(As + ar * G2_ASTR + ac,                                 \
                       A + (size_t)(row0 + ar) * K + (k0) + ac);               \
            const int br = id >> 4, bc = (id & 15) * 8;                        \
            const int col = col0 + bc;                                         \
            const int sz = (col + 8 <= N) ? 16 : 0;                            \
            cp_async16z(Bs + br * G2_BSTR + bc,                                \
                        B + (size_t)((k0) + br) * N + (sz ? col : 0), sz);     \
        }                                                                      \
    }

    G2_STAGE(0, 0);
    cp_commit();
    G2_STAGE(1, 64);
    cp_commit();

    for (int kt = 0; kt < nkt; kt++) {
        if (kt + 1 < nkt) { cp_wait<1>(); } else { cp_wait<0>(); }
        __syncthreads();

        // prefetch stage kt+2 (overlaps with compute below)
        if (kt + 2 < nkt) {
            const int pb = (kt + 2) % 3;
            G2_STAGE(pb, (kt + 2) << 6);
            cp_commit();
        }

        const uint32_t abase = smb + ((kt % 3) * G2_STG) * 2;
        const uint32_t bbase = abase + G2_AH * 2;

#pragma unroll
        for (int kh = 0; kh < 2; kh++) {
            // B fragments: 4 x ldsm_t covers 32 k-rows x 32 n-cols
            uint32_t bf[4][2][2];
            const uint32_t baddr =
                bbase + (uint32_t)((kh * 32 + lane) * G2_BSTR + wn * 32) * 2;
#pragma unroll
            for (int nt = 0; nt < 4; nt++) {
                uint32_t rr[4];
                ldsm_x4_t(rr, baddr + nt * 16);
                bf[nt][0][0] = rr[0]; bf[nt][0][1] = rr[1];
                bf[nt][1][0] = rr[2]; bf[nt][1][1] = rr[3];
            }
            const uint32_t aaddr =
                abase + (uint32_t)((wm * 64 + (lane & 15)) * G2_ASTR +
                                   (lane >> 4) * 8 + kh * 32) * 2;
#pragma unroll
            for (int mt = 0; mt < 4; mt++) {
                uint32_t a0[4], a1[4];
                ldsm_x4(a0, aaddr + mt * (16 * G2_ASTR * 2));
                ldsm_x4(a1, aaddr + mt * (16 * G2_ASTR * 2) + 32);
#pragma unroll
                for (int nt = 0; nt < 4; nt++) {
                    mma_f16(acc[mt][nt], a0, bf[nt][0]);
                    mma_f16(acc[mt][nt], a1, bf[nt][1]);
                }
            }
        }
    }

#pragma unroll
    for (int mt = 0; mt < 4; mt++) {
        const int gr0 = row0 + wm * 64 + mt * 16 + g;
#pragma unroll
        for (int nt = 0; nt < 4; nt++) {
            const int gc = col0 + wn * 32 + nt * 8 + 2 * tig;
            if (gc < N) {
                if (HALF_OUT) {
                    __half* C = (__half*)Cv;
                    *(__half2*)(C + (size_t)gr0 * N + gc) =
                        __floats2half2_rn(acc[mt][nt][0], acc[mt][nt][1]);
                    *(__half2*)(C + (size_t)(gr0 + 8) * N + gc) =
                        __floats2half2_rn(acc[mt][nt][2], acc[mt][nt][3]);
                } else {
                    float* C = (float*)Cv;
                    *(float2*)(C + (size_t)gr0 * N + gc) =
                        make_float2(acc[mt][nt][0], acc[mt][nt][1]);
                    *(float2*)(C + (size_t)(gr0 + 8) * N + gc) =
                        make_float2(acc[mt][nt][2], acc[mt][nt][3]);
                }
            }
        }
    }
}

// ---------------------------------------------------------------------------
// RMSNorm / RoPE (unchanged)
// ---------------------------------------------------------------------------
__global__ __launch_bounds__(128)
void rmsnorm_h(const __half* __restrict__ kv, const float* __restrict__ w,
               __half* __restrict__ out)
{
    __shared__ float red[4];
    const int tok = blockIdx.x;
    const int t = threadIdx.x;
    const __half* row = kv + (size_t)tok * 576;
    float v[4];
    float s = 0.0f;
#pragma unroll
    for (int u = 0; u < 4; u++) {
        v[u] = __half2float(row[t + u * 128]);
        s = fmaf(v[u], v[u], s);
    }
#pragma unroll
    for (int off = 16; off > 0; off >>= 1)
        s += __shfl_down_sync(0xffffffffu, s, off);
    if ((t & 31) == 0) red[t >> 5] = s;
    __syncthreads();
    const float tot = red[0] + red[1] + red[2] + red[3];
    const float r = rsqrtf(tot * (1.0f / 512.0f) + 1e-6f);
    __half* orow = out + (size_t)tok * 512;
#pragma unroll
    for (int u = 0; u < 4; u++) {
        const int idx = t + u * 128;
        orow[idx] = __float2half_rn(v[u] * r * w[idx]);
    }
}

__global__ __launch_bounds__(512)
void rope_qh(__half* __restrict__ q)
{
    const int tok = blockIdx.x;
    const int h = threadIdx.x >> 5;
    const int i = threadIdx.x & 31;
    const int s = tok & (SEQ - 1);
    const float e = (float)(2 * i) * (1.0f / 64.0f);
    const float freq = 1.0f / powf(10000.0f, e);
    float sn, c;
    sincosf((float)s * freq, &sn, &c);
    __half2* p = (__half2*)(q + (size_t)tok * 2048 + h * 128 + 64) + i;
    const float2 v = __half22float2(*p);
    *p = __floats2half2_rn(v.x * c - v.y * sn, v.y * c + v.x * sn);
}

__global__ __launch_bounds__(32)
void rope_kh(const __half* __restrict__ kv, __half* __restrict__ kpe)
{
    const int tok = blockIdx.x;
    const int i = threadIdx.x;
    const int s = tok & (SEQ - 1);
    const float e = (float)(2 * i) * (1.0f / 64.0f);
    const float freq = 1.0f / powf(10000.0f, e);
    float sn, c;
    sincosf((float)s * freq, &sn, &c);
    const float x1 = __half2float(kv[(size_t)tok * 576 + 512 + 2 * i]);
    const float x2 = __half2float(kv[(size_t)tok * 576 + 512 + 2 * i + 1]);
    ((__half2*)(kpe + (size_t)tok * 64))[i] =
        __floats2half2_rn(x1 * c - x2 * sn, x2 * c + x1 * sn);
}

// ---------------------------------------------------------------------------
// Flash attention v3 (unchanged from R10 — passing at ~110us)
// ---------------------------------------------------------------------------
#define FV_Q  0
#define FV_K0 17408
#define FV_K1 26112
#define FV_V0 34816
#define FV_V1 43520
#define FLASH_SMEM (52224 * 2)

__global__ __launch_bounds__(256)
void flash_v3(const __half* __restrict__ qh, const __half* __restrict__ kvd,
              const __half* __restrict__ kpe, __half* __restrict__ o)
{
    extern __shared__ __half smh[];
    const uint32_t smb = (uint32_t)__cvta_generic_to_shared(smh);

    const int t = threadIdx.x;
    const int lane = t & 31, w = t >> 5;
    const int g = lane >> 2, tig = lane & 3;
    const int qb = blockIdx.x, h = blockIdx.y, b = blockIdx.z;
    const int q0 = qb * 128;

#pragma unroll
    for (int i = 0; i < 8; i++) {
        const int id = t + i * 256;
        const int r = id >> 4, c = (id & 15) * 8;
        *(uint4*)(smh + FV_Q + r * 136 + c) =
            *(const uint4*)(qh + (size_t)(b * SEQ + q0 + r) * 2048 + h * 128 + c);
    }

#define FV_STAGE(koff, voff, ktile)                                            \
    {                                                                          \
        const int k0_ = (ktile) * 64;                                          \
        _Pragma("unroll")                                                      \
        for (int i = 0; i < 4; i++) {                                          \
            const int id = t + i * 256;                                        \
            const int r = id >> 4, c8 = id & 15;                               \
            const size_t tok = (size_t)(b * SEQ + k0_ + r);                    \
            const __half* ks = (c8 < 8)                                        \
                ? kvd + (tok * 16 + h) * 192 + c8 * 8                          \
                : kpe + tok * 64 + (c8 - 8) * 8;                               \
            cp_async16(smh + (koff) + r * 136 + c8 * 8, ks);                   \
            cp_async16(smh + (voff) + r * 136 + c8 * 8,                        \
                       kvd + (tok * 16 + h) * 192 + 64 + c8 * 8);              \
        }                                                                      \
    }

    FV_STAGE(FV_K0, FV_V0, 0);
    cp_commit();

    float oacc[16][4];
#pragma unroll
    for (int nt = 0; nt < 16; nt++)
#pragma unroll
        for (int i = 0; i < 4; i++) oacc[nt][i] = 0.f;

    float m0 = -1e30f, m1 = -1e30f, l0 = 0.f, l1 = 0.f;

    const uint32_t qByte =
        smb + (uint32_t)((FV_Q + (w * 16 + (lane & 15)) * 136 + (lane >> 4) * 8)) * 2;
    const uint32_t kRow = (uint32_t)((lane & 7) * 136 + (lane >> 3) * 8) * 2;
    const uint32_t vRow = (uint32_t)(lane * 136) * 2;

    const int nkt = 2 * (qb + 1);
    for (int kt = 0; kt < nkt; kt++) {
        cp_wait<0>();
        __syncthreads();
        const int bsel = kt & 1;
        if (kt + 1 < nkt) {
            if (bsel) { FV_STAGE(FV_K0, FV_V0, kt + 1); }
            else      { FV_STAGE(FV_K1, FV_V1, kt + 1); }
            cp_commit();
        }
        const uint32_t kBase = smb + (bsel ? FV_K1 : FV_K0) * 2 + kRow;
        const uint32_t vBase = smb + (bsel ? FV_V1 : FV_V0) * 2 + vRow;
        const int k0 = kt * 64;

        float sacc[8][4];
#pragma unroll
        for (int nt = 0; nt < 8; nt++)
#pragma unroll
            for (int i = 0; i < 4; i++) sacc[nt][i] = 0.f;

#pragma unroll
        for (int dch = 0; dch < 4; dch++) {
            uint32_t a0[4], a1[4];
            ldsm_x4(a0, qByte + dch * 64);
            ldsm_x4(a1, qByte + dch * 64 + 32);
#pragma unroll
            for (int ng = 0; ng < 2; ng++) {
                uint32_t kb[4][2][2];
#pragma unroll
                for (int j = 0; j < 4; j++) {
                    uint32_t rr[4];
                    ldsm_x4(rr, kBase + (ng * 4 + j) * (8 * 136 * 2) + dch * 64);
                    kb[j][0][0] = rr[0]; kb[j][0][1] = rr[1];
                    kb[j][1][0] = rr[2]; kb[j][1][1] = rr[3];
                }
#pragma unroll
                for (int j = 0; j < 4; j++) {
                    mma_f16(sacc[ng * 4 + j], a0, kb[j][0]);
                    mma_f16(sacc[ng * 4 + j], a1, kb[j][1]);
                }
            }
        }

        if (kt >= nkt - 2) {
            const int row0 = q0 + w * 16 + g;
#pragma unroll
            for (int nt = 0; nt < 8; nt++) {
                const int col = k0 + nt * 8 + 2 * tig;
                if (col     > row0)     sacc[nt][0] = -1e30f;
                if (col + 1 > row0)     sacc[nt][1] = -1e30f;
                if (col     > row0 + 8) sacc[nt][2] = -1e30f;
                if (col + 1 > row0 + 8) sacc[nt][3] = -1e30f;
            }
        }

        float mx0 = m0, mx1 = m1;
#pragma unroll
        for (int nt = 0; nt < 8; nt++) {
            mx0 = fmaxf(mx0, fmaxf(sacc[nt][0], sacc[nt][1]));
            mx1 = fmaxf(mx1, fmaxf(sacc[nt][2], sacc[nt][3]));
        }
        mx0 = fmaxf(mx0, __shfl_xor_sync(0xffffffffu, mx0, 1));
        mx0 = fmaxf(mx0, __shfl_xor_sync(0xffffffffu, mx0, 2));
        mx1 = fmaxf(mx1, __shfl_xor_sync(0xffffffffu, mx1, 1));
        mx1 = fmaxf(mx1, __shfl_xor_sync(0xffffffffu, mx1, 2));
        const float f0 = exp2f(m0 - mx0);
        const float f1 = exp2f(m1 - mx1);
        float s0 = 0.f, s1 = 0.f;
        uint32_t ph[8][2];
#pragma unroll
        for (int nt = 0; nt < 8; nt++) {
            const float p00 = exp2f(sacc[nt][0] - mx0);
            const float p01 = exp2f(sacc[nt][1] - mx0);
            const float p10 = exp2f(sacc[nt][2] - mx1);
            const float p11 = exp2f(sacc[nt][3] - mx1);
            s0 += p00 + p01;
            s1 += p10 + p11;
            ph[nt][0] = h2_to_u32(__floats2half2_rn(p00, p01));
            ph[nt][1] = h2_to_u32(__floats2half2_rn(p10, p11));
        }
        s0 += __shfl_xor_sync(0xffffffffu, s0, 1);
        s0 += __shfl_xor_sync(0xffffffffu, s0, 2);
        s1 += __shfl_xor_sync(0xffffffffu, s1, 1);
        s1 += __shfl_xor_sync(0xffffffffu, s1, 2);
        l0 = l0 * f0 + s0;
        l1 = l1 * f1 + s1;
        m0 = mx0;
        m1 = mx1;
#pragma unroll
        for (int nt = 0; nt < 16; nt++) {
            oacc[nt][0] *= f0; oacc[nt][1] *= f0;
            oacc[nt][2] *= f1; oacc[nt][3] *= f1;
        }

#pragma unroll
        for (int vch = 0; vch < 2; vch++) {
            const uint32_t A0[4] = {ph[4 * vch + 0][0], ph[4 * vch + 0][1],
                                    ph[4 * vch + 1][0], ph[4 * vch + 1][1]};
            const uint32_t A1[4] = {ph[4 * vch + 2][0], ph[4 * vch + 2][1],
                                    ph[4 * vch + 3][0], ph[4 * vch + 3][1]};
#pragma unroll
            for (int ng = 0; ng < 4; ng++) {
                uint32_t vb[4][2][2];
#pragma unroll
                for (int j = 0; j < 4; j++) {
                    uint32_t rr[4];
                    ldsm_x4_t(rr, vBase + vch * (32 * 136 * 2) + (ng * 4 + j) * 16);
                    vb[j][0][0] = rr[0]; vb[j][0][1] = rr[1];
                    vb[j][1][0] = rr[2]; vb[j][1][1] = rr[3];
                }
#pragma unroll
                for (int j = 0; j < 4; j++) {
                    mma_f16(oacc[ng * 4 + j], A0, vb[j][0]);
                    mma_f16(oacc[ng * 4 + j], A1, vb[j][1]);
                }
            }
        }
    }

    const float inv0 = 1.0f / l0;
    const float inv1 = 1.0f / l1;
    const size_t r0 = (size_t)(b * SEQ + q0 + w * 16 + g) * 2048 + h * 128;
    const size_t r1 = (size_t)(b * SEQ + q0 + w * 16 + g + 8) * 2048 + h * 128;
#pragma unroll
    for (int nt = 0; nt < 16; nt++) {
        const int col = nt * 8 + 2 * tig;
        *(__half2*)(o + r0 + col) =
            __floats2half2_rn(oacc[nt][0] * inv0, oacc[nt][1] * inv0);
        *(__half2*)(o + r1 + col) =
            __floats2half2_rn(oacc[nt][2] * inv1, oacc[nt][3] * inv1);
    }
}

// ---------------------------------------------------------------------------
// Launch
// ---------------------------------------------------------------------------
extern "C" void kernel_launch(void* const* d_in, const int* in_sizes, int n_in,
                              void* d_out, int out_size)
{
    (void)in_sizes; (void)n_in; (void)out_size;
    const float* x          = (const float*)d_in[0];
    const float* w_query    = (const float*)d_in[1];
    const float* wkv_a      = (const float*)d_in[2];
    const float* wkv_b      = (const float*)d_in[3];
    const float* kv_norm_w  = (const float*)d_in[4];
    const float* out_proj_w = (const float*)d_in[5];
    float* out = (float*)d_out;

    __half *xh, *qh, *kvh, *kvch, *kpeh, *kvdech, *attnh, *wqh, *wkvah, *wkvbh, *wouth;
    cudaGetSymbolAddress((void**)&xh,     g_xh);
    cudaGetSymbolAddress((void**)&qh,     g_qh);
    cudaGetSymbolAddress((void**)&kvh,    g_kvh);
    cudaGetSymbolAddress((void**)&kvch,   g_kvch);
    cudaGetSymbolAddress((void**)&kpeh,   g_kpeh);
    cudaGetSymbolAddress((void**)&kvdech, g_kvdech);
    cudaGetSymbolAddress((void**)&attnh,  g_attnh);
    cudaGetSymbolAddress((void**)&wqh,    g_wqh);
    cudaGetSymbolAddress((void**)&wkvah,  g_wkvah);
    cudaGetSymbolAddress((void**)&wkvbh,  g_wkvbh);
    cudaGetSymbolAddress((void**)&wouth,  g_wouth);

    cudaFuncSetAttribute(gemm_f16<true>,
                         cudaFuncAttributeMaxDynamicSharedMemorySize, GEMM_SMEM);
    cudaFuncSetAttribute(gemm_f16<false>,
                         cudaFuncAttributeMaxDynamicSharedMemorySize, GEMM_SMEM);
    cudaFuncSetAttribute(flash_v3,
                         cudaFuncAttributeMaxDynamicSharedMemorySize, FLASH_SMEM);

    // 1/sqrt(128) * log2(e): flash softmax runs in base-2 domain
    const float qscale = 0.08838834764831845f * 1.44269504088896340736f;

    prep_half<<<(TOKS * 2048 / 4 + 255) / 256, 256>>>(x, xh, 1.0f, TOKS * 2048 / 4);
    prep_half<<<(2048 * 2048 / 4 + 255) / 256, 256>>>(w_query, wqh, qscale, 2048 * 2048 / 4);
    prep_half<<<(2048 * 576 / 4 + 255) / 256, 256>>>(wkv_a, wkvah, 1.0f, 2048 * 576 / 4);
    prep_half<<<(512 * 3072 / 4 + 255) / 256, 256>>>(wkv_b, wkvbh, 1.0f, 512 * 3072 / 4);
    prep_half<<<(2048 * 2048 / 4 + 255) / 256, 256>>>(out_proj_w, wouth, 1.0f, 2048 * 2048 / 4);

    // q = x @ (w_query * qscale)  [4096,2048] fp16
    gemm_f16<true><<<dim3(16, 32), 256, GEMM_SMEM>>>(xh, wqh, qh, TOKS, 2048, 2048);
    // kv = x @ wkv_a              [4096,576] fp16
    gemm_f16<true><<<dim3(5, 32), 256, GEMM_SMEM>>>(xh, wkvah, kvh, TOKS, 576, 2048);
    // rope q_pe in place
    rope_qh<<<TOKS, 512>>>(qh);
    // rmsnorm latent
    rmsnorm_h<<<TOKS, 128>>>(kvh, kv_norm_w, kvch);
    // rope k_pe
    rope_kh<<<TOKS, 32>>>(kvh, kpeh);
    // kv_dec = kvc @ wkv_b        [4096,3072] fp16
    gemm_f16<true><<<dim3(24, 32), 256, GEMM_SMEM>>>(kvch, wkvbh, kvdech, TOKS, 3072, 512);
    // causal flash attention (register-resident P, cp.async K/V)
    flash_v3<<<dim3(SEQ / 128, 16, 2), 256, FLASH_SMEM>>>(qh, kvdech, kpeh, attnh);
    // out = attn @ out_proj_w     [4096,2048] fp32
    gemm_f16<false><<<dim3(16, 32), 256, GEMM_SMEM>>>(attnh, wouth, out, TOKS, 2048, 2048);
}

// round 13
// speedup vs baseline: 3.1607x; 1.0033x over previous
#include <cuda_runtime.h>
#include <cuda_fp16.h>
#include <math.h>
#include <stdint.h>

// B=2, S=2048, T=4096, D_IN=2048, H=16, QK_HEAD=128, V_HEAD=128, KV_RANK=512
#define TOKS 4096
#define SEQ  2048

// ---------------------------------------------------------------------------
// Scratch (fp16)
// ---------------------------------------------------------------------------
__device__ __half g_xh[(size_t)TOKS * 2048];
__device__ __half g_qh[(size_t)TOKS * 2048];
__device__ __half g_kvh[(size_t)TOKS * 576];
__device__ __half g_kvch[(size_t)TOKS * 512];
__device__ __half g_kpeh[(size_t)TOKS * 64];
__device__ __half g_kvdech[(size_t)TOKS * 3072];
__device__ __half g_attnh[(size_t)TOKS * 2048];
__device__ __half g_wqh[(size_t)2048 * 2048];
__device__ __half g_wkvah[(size_t)2048 * 576];
__device__ __half g_wkvbh[(size_t)512 * 3072];
__device__ __half g_wouth[(size_t)2048 * 2048];

// ---------------------------------------------------------------------------
// Helpers
// ---------------------------------------------------------------------------
__device__ __forceinline__ uint32_t h2_to_u32(__half2 h) {
    union { __half2 h2; uint32_t u; } cvt;
    cvt.h2 = h;
    return cvt.u;
}

__device__ __forceinline__ void mma_f16(float* d, const uint32_t* a, const uint32_t* b) {
    asm volatile(
        "mma.sync.aligned.m16n8k16.row.col.f32.f16.f16.f32 "
        "{%0,%1,%2,%3}, {%4,%5,%6,%7}, {%8,%9}, {%0,%1,%2,%3};\n"
        : "+f"(d[0]), "+f"(d[1]), "+f"(d[2]), "+f"(d[3])
        : "r"(a[0]), "r"(a[1]), "r"(a[2]), "r"(a[3]), "r"(b[0]), "r"(b[1]));
}
__device__ __forceinline__ void ldsm_x4(uint32_t* r, uint32_t addr) {
    asm volatile("ldmatrix.sync.aligned.m8n8.x4.shared.b16 {%0,%1,%2,%3}, [%4];\n"
                 : "=r"(r[0]), "=r"(r[1]), "=r"(r[2]), "=r"(r[3]) : "r"(addr));
}
__device__ __forceinline__ void ldsm_x4_t(uint32_t* r, uint32_t addr) {
    asm volatile("ldmatrix.sync.aligned.m8n8.x4.trans.shared.b16 {%0,%1,%2,%3}, [%4];\n"
                 : "=r"(r[0]), "=r"(r[1]), "=r"(r[2]), "=r"(r[3]) : "r"(addr));
}
__device__ __forceinline__ void cp_async16(void* smem_ptr, const void* gptr) {
    uint32_t saddr = (uint32_t)__cvta_generic_to_shared(smem_ptr);
    asm volatile("cp.async.cg.shared.global [%0], [%1], 16;\n"
                 :: "r"(saddr), "l"(gptr) : "memory");
}
__device__ __forceinline__ void cp_async16z(void* smem_ptr, const void* gptr, int sz) {
    uint32_t saddr = (uint32_t)__cvta_generic_to_shared(smem_ptr);
    asm volatile("cp.async.cg.shared.global [%0], [%1], 16, %2;\n"
                 :: "r"(saddr), "l"(gptr), "r"(sz) : "memory");
}
__device__ __forceinline__ void cp_commit() {
    asm volatile("cp.async.commit_group;\n" ::: "memory");
}
template <int N>
__device__ __forceinline__ void cp_wait() {
    asm volatile("cp.async.wait_group %0;\n" :: "n"(N) : "memory");
}

// ---------------------------------------------------------------------------
// Pre-pass kernels
// ---------------------------------------------------------------------------
__global__ __launch_bounds__(256)
void prep_half(const float* __restrict__ in, __half* __restrict__ out,
               float scale, int n4)
{
    const int i = blockIdx.x * 256 + threadIdx.x;
    if (i >= n4) return;
    const float4 v = ((const float4*)in)[i];
    __half2* o = (__half2*)out + (size_t)i * 2;
    o[0] = __floats2half2_rn(v.x * scale, v.y * scale);
    o[1] = __floats2half2_rn(v.z * scale, v.w * scale);
}

// Fused cast for three scale-1 weights (wkv_a | wkv_b | out_proj)
__global__ __launch_bounds__(256)
void prep3(const float* __restrict__ a, __half* __restrict__ ao, int na4,
           const float* __restrict__ b, __half* __restrict__ bo, int nb4,
           const float* __restrict__ c, __half* __restrict__ co, int nc4)
{
    const int i = blockIdx.x * 256 + threadIdx.x;
    const float* src;
    __half* dst;
    int j;
    if (i < na4)              { src = a; dst = ao; j = i; }
    else if (i < na4 + nb4)   { src = b; dst = bo; j = i - na4; }
    else if (i < na4 + nb4 + nc4) { src = c; dst = co; j = i - na4 - nb4; }
    else return;
    const float4 v = ((const float4*)src)[j];
    __half2* o = (__half2*)dst + (size_t)j * 2;
    o[0] = __floats2half2_rn(v.x, v.y);
    o[1] = __floats2half2_rn(v.z, v.w);
}

// ---------------------------------------------------------------------------
// FP16 GEMM: C[M,N] = A[M,K] @ B[K,N].
// BM=BN=128, BK=64, 256 thr / 8 warps, 2 CTAs/SM, 3-stage cp.async pipeline.
// ---------------------------------------------------------------------------
#define G2_ASTR 72
#define G2_BSTR 136
#define G2_AH (128 * G2_ASTR)
#define G2_BH (64 * G2_BSTR)
#define G2_STG (G2_AH + G2_BH)
#define GEMM_SMEM (3 * G2_STG * 2)

template <bool HALF_OUT>
__global__ __launch_bounds__(256, 2)
void gemm_f16(const __half* __restrict__ A, const __half* __restrict__ B,
              void* __restrict__ Cv, int M, int N, int K)
{
    extern __shared__ __half smh[];
    const uint32_t smb = (uint32_t)__cvta_generic_to_shared(smh);

    const int t = threadIdx.x;
    const int lane = t & 31, wid = t >> 5;
    const int g = lane >> 2, tig = lane & 3;
    const int wm = wid >> 2;
    const int wn = wid & 3;
    const int row0 = blockIdx.y * 128;
    const int col0 = blockIdx.x * 128;

    float acc[4][4][4];
#pragma unroll
    for (int mt = 0; mt < 4; mt++)
#pragma unroll
        for (int nt = 0; nt < 4; nt++)
#pragma unroll
            for (int i = 0; i < 4; i++) acc[mt][nt][i] = 0.f;

    const int nkt = K >> 6;

#define G2_STAGE(buf, k0)                                                      \
    {                                                                          \
        __half* As = smh + (buf) * G2_STG;                                     \
        __half* Bs = As + G2_AH;                                               \
        _Pragma("unroll")                                                      \
        for (int i = 0; i < 4; i++) {                                          \
            const int id = t + i * 256;                                        \
            const int ar = id >> 3, ac = (id & 7) * 8;                         \
            cp_async16(As + ar * G2_ASTR + ac,                                 \
                       A + (size_t)(row0 + ar) * K + (k0) + ac);               \
            const int br = id >> 4, bc = (id & 15) * 8;                        \
            const int col = col0 + bc;                                         \
            const int sz = (col + 8 <= N) ? 16 : 0;                            \
            cp_async16z(Bs + br * G2_BSTR + bc,                                \
                        B + (size_t)((k0) + br) * N + (sz ? col : 0), sz);     \
        }                                                                      \
    }

    G2_STAGE(0, 0);
    cp_commit();
    G2_STAGE(1, 64);
    cp_commit();

    for (int kt = 0; kt < nkt; kt++) {
        if (kt + 1 < nkt) { cp_wait<1>(); } else { cp_wait<0>(); }
        __syncthreads();

        if (kt + 2 < nkt) {
            const int pb = (kt + 2) % 3;
            G2_STAGE(pb, (kt + 2) << 6);
            cp_commit();
        }

        const uint32_t abase = smb + ((kt % 3) * G2_STG) * 2;
        const uint32_t bbase = abase + G2_AH * 2;

#pragma unroll
        for (int kh = 0; kh < 2; kh++) {
            uint32_t bf[4][2][2];
            const uint32_t baddr =
                bbase + (uint32_t)((kh * 32 + lane) * G2_BSTR + wn * 32) * 2;
#pragma unroll
            for (int nt = 0; nt < 4; nt++) {
                uint32_t rr[4];
                ldsm_x4_t(rr, baddr + nt * 16);
                bf[nt][0][0] = rr[0]; bf[nt][0][1] = rr[1];
                bf[nt][1][0] = rr[2]; bf[nt][1][1] = rr[3];
            }
            const uint32_t aaddr =
                abase + (uint32_t)((wm * 64 + (lane & 15)) * G2_ASTR +
                                   (lane >> 4) * 8 + kh * 32) * 2;
#pragma unroll
            for (int mt = 0; mt < 4; mt++) {
                uint32_t a0[4], a1[4];
                ldsm_x4(a0, aaddr + mt * (16 * G2_ASTR * 2));
                ldsm_x4(a1, aaddr + mt * (16 * G2_ASTR * 2) + 32);
#pragma unroll
                for (int nt = 0; nt < 4; nt++) {
                    mma_f16(acc[mt][nt], a0, bf[nt][0]);
                    mma_f16(acc[mt][nt], a1, bf[nt][1]);
                }
            }
        }
    }

#pragma unroll
    for (int mt = 0; mt < 4; mt++) {
        const int gr0 = row0 + wm * 64 + mt * 16 + g;
#pragma unroll
        for (int nt = 0; nt < 4; nt++) {
            const int gc = col0 + wn * 32 + nt * 8 + 2 * tig;
            if (gc < N) {
                if (HALF_OUT) {
                    __half* C = (__half*)Cv;
                    *(__half2*)(C + (size_t)gr0 * N + gc) =
                        __floats2half2_rn(acc[mt][nt][0], acc[mt][nt][1]);
                    *(__half2*)(C + (size_t)(gr0 + 8) * N + gc) =
                        __floats2half2_rn(acc[mt][nt][2], acc[mt][nt][3]);
                } else {
                    float* C = (float*)Cv;
                    *(float2*)(C + (size_t)gr0 * N + gc) =
                        make_float2(acc[mt][nt][0], acc[mt][nt][1]);
                    *(float2*)(C + (size_t)(gr0 + 8) * N + gc) =
                        make_float2(acc[mt][nt][2], acc[mt][nt][3]);
                }
            }
        }
    }
}

// ---------------------------------------------------------------------------
// RMSNorm / RoPE (unchanged)
// ---------------------------------------------------------------------------
__global__ __launch_bounds__(128)
void rmsnorm_h(const __half* __restrict__ kv, const float* __restrict__ w,
               __half* __restrict__ out)
{
    __shared__ float red[4];
    const int tok = blockIdx.x;
    const int t = threadIdx.x;
    const __half* row = kv + (size_t)tok * 576;
    float v[4];
    float s = 0.0f;
#pragma unroll
    for (int u = 0; u < 4; u++) {
        v[u] = __half2float(row[t + u * 128]);
        s = fmaf(v[u], v[u], s);
    }
#pragma unroll
    for (int off = 16; off > 0; off >>= 1)
        s += __shfl_down_sync(0xffffffffu, s, off);
    if ((t & 31) == 0) red[t >> 5] = s;
    __syncthreads();
    const float tot = red[0] + red[1] + red[2] + red[3];
    const float r = rsqrtf(tot * (1.0f / 512.0f) + 1e-6f);
    __half* orow = out + (size_t)tok * 512;
#pragma unroll
    for (int u = 0; u < 4; u++) {
        const int idx = t + u * 128;
        orow[idx] = __float2half_rn(v[u] * r * w[idx]);
    }
}

__global__ __launch_bounds__(512)
void rope_qh(__half* __restrict__ q)
{
    const int tok = blockIdx.x;
    const int h = threadIdx.x >> 5;
    const int i = threadIdx.x & 31;
    const int s = tok & (SEQ - 1);
    const float e = (float)(2 * i) * (1.0f / 64.0f);
    const float freq = 1.0f / powf(10000.0f, e);
    float sn, c;
    sincosf((float)s * freq, &sn, &c);
    __half2* p = (__half2*)(q + (size_t)tok * 2048 + h * 128 + 64) + i;
    const float2 v = __half22float2(*p);
    *p = __floats2half2_rn(v.x * c - v.y * sn, v.y * c + v.x * sn);
}

__global__ __launch_bounds__(32)
void rope_kh(const __half* __restrict__ kv, __half* __restrict__ kpe)
{
    const int tok = blockIdx.x;
    const int i = threadIdx.x;
    const int s = tok & (SEQ - 1);
    const float e = (float)(2 * i) * (1.0f / 64.0f);
    const float freq = 1.0f / powf(10000.0f, e);
    float sn, c;
    sincosf((float)s * freq, &sn, &c);
    const float x1 = __half2float(kv[(size_t)tok * 576 + 512 + 2 * i]);
    const float x2 = __half2float(kv[(size_t)tok * 576 + 512 + 2 * i + 1]);
    ((__half2*)(kpe + (size_t)tok * 64))[i] =
        __floats2half2_rn(x1 * c - x2 * sn, x2 * c + x1 * sn);
}

// ---------------------------------------------------------------------------
// Flash attention v3 + fully-masked-warp skip on the final k-tile.
// ---------------------------------------------------------------------------
#define FV_Q  0
#define FV_K0 17408
#define FV_K1 26112
#define FV_V0 34816
#define FV_V1 43520
#define FLASH_SMEM (52224 * 2)

__global__ __launch_bounds__(256)
void flash_v3(const __half* __restrict__ qh, const __half* __restrict__ kvd,
              const __half* __restrict__ kpe, __half* __restrict__ o)
{
    extern __shared__ __half smh[];
    const uint32_t smb = (uint32_t)__cvta_generic_to_shared(smh);

    const int t = threadIdx.x;
    const int lane = t & 31, w = t >> 5;
    const int g = lane >> 2, tig = lane & 3;
    const int qb = blockIdx.x, h = blockIdx.y, b = blockIdx.z;
    const int q0 = qb * 128;

#pragma unroll
    for (int i = 0; i < 8; i++) {
        const int id = t + i * 256;
        const int r = id >> 4, c = (id & 15) * 8;
        *(uint4*)(smh + FV_Q + r * 136 + c) =
            *(const uint4*)(qh + (size_t)(b * SEQ + q0 + r) * 2048 + h * 128 + c);
    }

#define FV_STAGE(koff, voff, ktile)                                            \
    {                                                                          \
        const int k0_ = (ktile) * 64;                                          \
        _Pragma("unroll")                                                      \
        for (int i = 0; i < 4; i++) {                                          \
            const int id = t + i * 256;                                        \
            const int r = id >> 4, c8 = id & 15;                               \
            const size_t tok = (size_t)(b * SEQ + k0_ + r);                    \
            const __half* ks = (c8 < 8)                                        \
                ? kvd + (tok * 16 + h) * 192 + c8 * 8                          \
                : kpe + tok * 64 + (c8 - 8) * 8;                               \
            cp_async16(smh + (koff) + r * 136 + c8 * 8, ks);                   \
            cp_async16(smh + (voff) + r * 136 + c8 * 8,                        \
                       kvd + (tok * 16 + h) * 192 + 64 + c8 * 8);              \
        }                                                                      \
    }

    FV_STAGE(FV_K0, FV_V0, 0);
    cp_commit();

    float oacc[16][4];
#pragma unroll
    for (int nt = 0; nt < 16; nt++)
#pragma unroll
        for (int i = 0; i < 4; i++) oacc[nt][i] = 0.f;

    float m0 = -1e30f, m1 = -1e30f, l0 = 0.f, l1 = 0.f;

    const uint32_t qByte =
        smb + (uint32_t)((FV_Q + (w * 16 + (lane & 15)) * 136 + (lane >> 4) * 8)) * 2;
    const uint32_t kRow = (uint32_t)((lane & 7) * 136 + (lane >> 3) * 8) * 2;
    const uint32_t vRow = (uint32_t)(lane * 136) * 2;

    const int nkt = 2 * (qb + 1);
    for (int kt = 0; kt < nkt; kt++) {
        cp_wait<0>();
        __syncthreads();
        const int bsel = kt & 1;
        if (kt + 1 < nkt) {
            if (bsel) { FV_STAGE(FV_K0, FV_V0, kt + 1); }
            else      { FV_STAGE(FV_K1, FV_V1, kt + 1); }
            cp_commit();
        }

        // Final k-tile covers keys [128qb+64,128qb+128): warps 0-3 own q-rows
        // [128qb,128qb+64) which are ALL above the diagonal -> fully masked.
        // Warp-uniform skip (staging + barriers already done above).
        if (kt == nkt - 1 && w < 4) continue;

        const uint32_t kBase = smb + (bsel ? FV_K1 : FV_K0) * 2 + kRow;
        const uint32_t vBase = smb + (bsel ? FV_V1 : FV_V0) * 2 + vRow;
        const int k0 = kt * 64;

        float sacc[8][4];
#pragma unroll
        for (int nt = 0; nt < 8; nt++)
#pragma unroll
            for (int i = 0; i < 4; i++) sacc[nt][i] = 0.f;

#pragma unroll
        for (int dch = 0; dch < 4; dch++) {
            uint32_t a0[4], a1[4];
            ldsm_x4(a0, qByte + dch * 64);
            ldsm_x4(a1, qByte + dch * 64 + 32);
#pragma unroll
            for (int ng = 0; ng < 2; ng++) {
                uint32_t kb[4][2][2];
#pragma unroll
                for (int j = 0; j < 4; j++) {
                    uint32_t rr[4];
                    ldsm_x4(rr, kBase + (ng * 4 + j) * (8 * 136 * 2) + dch * 64);
                    kb[j][0][0] = rr[0]; kb[j][0][1] = rr[1];
                    kb[j][1][0] = rr[2]; kb[j][1][1] = rr[3];
                }
#pragma unroll
                for (int j = 0; j < 4; j++) {
                    mma_f16(sacc[ng * 4 + j], a0, kb[j][0]);
                    mma_f16(sacc[ng * 4 + j], a1, kb[j][1]);
                }
            }
        }

        if (kt >= nkt - 2) {
            const int row0 = q0 + w * 16 + g;
#pragma unroll
            for (int nt = 0; nt < 8; nt++) {
                const int col = k0 + nt * 8 + 2 * tig;
                if (col     > row0)     sacc[nt][0] = -1e30f;
                if (col + 1 > row0)     sacc[nt][1] = -1e30f;
                if (col     > row0 + 8) sacc[nt][2] = -1e30f;
                if (col + 1 > row0 + 8) sacc[nt][3] = -1e30f;
            }
        }

        float mx0 = m0, mx1 = m1;
#pragma unroll
        for (int nt = 0; nt < 8; nt++) {
            mx0 = fmaxf(mx0, fmaxf(sacc[nt][0], sacc[nt][1]));
            mx1 = fmaxf(mx1, fmaxf(sacc[nt][2], sacc[nt][3]));
        }
        mx0 = fmaxf(mx0, __shfl_xor_sync(0xffffffffu, mx0, 1));
        mx0 = fmaxf(mx0, __shfl_xor_sync(0xffffffffu, mx0, 2));
        mx1 = fmaxf(mx1, __shfl_xor_sync(0xffffffffu, mx1, 1));
        mx1 = fmaxf(mx1, __shfl_xor_sync(0xffffffffu, mx1, 2));
        const float f0 = exp2f(m0 - mx0);
        const float f1 = exp2f(m1 - mx1);
        float s0 = 0.f, s1 = 0.f;
        uint32_t ph[8][2];
#pragma unroll
        for (int nt = 0; nt < 8; nt++) {
            const float p00 = exp2f(sacc[nt][0] - mx0);
            const float p01 = exp2f(sacc[nt][1] - mx0);
            const float p10 = exp2f(sacc[nt][2] - mx1);
            const float p11 = exp2f(sacc[nt][3] - mx1);
            s0 += p00 + p01;
            s1 += p10 + p11;
            ph[nt][0] = h2_to_u32(__floats2half2_rn(p00, p01));
            ph[nt][1] = h2_to_u32(__floats2half2_rn(p10, p11));
        }
        s0 += __shfl_xor_sync(0xffffffffu, s0, 1);
        s0 += __shfl_xor_sync(0xffffffffu, s0, 2);
        s1 += __shfl_xor_sync(0xffffffffu, s1, 1);
        s1 += __shfl_xor_sync(0xffffffffu, s1, 2);
        l0 = l0 * f0 + s0;
        l1 = l1 * f1 + s1;
        m0 = mx0;
        m1 = mx1;
#pragma unroll
        for (int nt = 0; nt < 16; nt++) {
            oacc[nt][0] *= f0; oacc[nt][1] *= f0;
            oacc[nt][2] *= f1; oacc[nt][3] *= f1;
        }

#pragma unroll
        for (int vch = 0; vch < 2; vch++) {
            const uint32_t A0[4] = {ph[4 * vch + 0][0], ph[4 * vch + 0][1],
                                    ph[4 * vch + 1][0], ph[4 * vch + 1][1]};
            const uint32_t A1[4] = {ph[4 * vch + 2][0], ph[4 * vch + 2][1],
                                    ph[4 * vch + 3][0], ph[4 * vch + 3][1]};
#pragma unroll
            for (int ng = 0; ng < 4; ng++) {
                uint32_t vb[4][2][2];
#pragma unroll
                for (int j = 0; j < 4; j++) {
                    uint32_t rr[4];
                    ldsm_x4_t(rr, vBase + vch * (32 * 136 * 2) + (ng * 4 + j) * 16);
                    vb[j][0][0] = rr[0]; vb[j][0][1] = rr[1];
                    vb[j][1][0] = rr[2]; vb[j][1][1] = rr[3];
                }
#pragma unroll
                for (int j = 0; j < 4; j++) {
                    mma_f16(oacc[ng * 4 + j], A0, vb[j][0]);
                    mma_f16(oacc[ng * 4 + j], A1, vb[j][1]);
                }
            }
        }
    }

    const float inv0 = 1.0f / l0;
    const float inv1 = 1.0f / l1;
    const size_t r0 = (size_t)(b * SEQ + q0 + w * 16 + g) * 2048 + h * 128;
    const size_t r1 = (size_t)(b * SEQ + q0 + w * 16 + g + 8) * 2048 + h * 128;
#pragma unroll
    for (int nt = 0; nt < 16; nt++) {
        const int col = nt * 8 + 2 * tig;
        *(__half2*)(o + r0 + col) =
            __floats2half2_rn(oacc[nt][0] * inv0, oacc[nt][1] * inv0);
        *(__half2*)(o + r1 + col) =
            __floats2half2_rn(oacc[nt][2] * inv1, oacc[nt][3] * inv1);
    }
}

// ---------------------------------------------------------------------------
// Launch (idx 3 = gemm_f16 G1 for the ncu capture window)
// ---------------------------------------------------------------------------
extern "C" void kernel_launch(void* const* d_in, const int* in_sizes, int n_in,
                              void* d_out, int out_size)
{
    (void)in_sizes; (void)n_in; (void)out_size;
    const float* x          = (const float*)d_in[0];
    const float* w_query    = (const float*)d_in[1];
    const float* wkv_a      = (const float*)d_in[2];
    const float* wkv_b      = (const float*)d_in[3];
    const float* kv_norm_w  = (const float*)d_in[4];
    const float* out_proj_w = (const float*)d_in[5];
    float* out = (float*)d_out;

    __half *xh, *qh, *kvh, *kvch, *kpeh, *kvdech, *attnh, *wqh, *wkvah, *wkvbh, *wouth;
    cudaGetSymbolAddress((void**)&xh,     g_xh);
    cudaGetSymbolAddress((void**)&qh,     g_qh);
    cudaGetSymbolAddress((void**)&kvh,    g_kvh);
    cudaGetSymbolAddress((void**)&kvch,   g_kvch);
    cudaGetSymbolAddress((void**)&kpeh,   g_kpeh);
    cudaGetSymbolAddress((void**)&kvdech, g_kvdech);
    cudaGetSymbolAddress((void**)&attnh,  g_attnh);
    cudaGetSymbolAddress((void**)&wqh,    g_wqh);
    cudaGetSymbolAddress((void**)&wkvah,  g_wkvah);
    cudaGetSymbolAddress((void**)&wkvbh,  g_wkvbh);
    cudaGetSymbolAddress((void**)&wouth,  g_wouth);

    cudaFuncSetAttribute(gemm_f16<true>,
                         cudaFuncAttributeMaxDynamicSharedMemorySize, GEMM_SMEM);
    cudaFuncSetAttribute(gemm_f16<false>,
                         cudaFuncAttributeMaxDynamicSharedMemorySize, GEMM_SMEM);
    cudaFuncSetAttribute(flash_v3,
                         cudaFuncAttributeMaxDynamicSharedMemorySize, FLASH_SMEM);

    // 1/sqrt(128) * log2(e): flash softmax runs in base-2 domain
    const float qscale = 0.08838834764831845f * 1.44269504088896340736f;

    // idx0: x cast
    prep_half<<<(TOKS * 2048 / 4 + 255) / 256, 256>>>(x, xh, 1.0f, TOKS * 2048 / 4);
    // idx1: w_query cast (scale folded)
    prep_half<<<(2048 * 2048 / 4 + 255) / 256, 256>>>(w_query, wqh, qscale, 2048 * 2048 / 4);
    // idx2: fused cast of wkv_a | wkv_b | out_proj (all scale 1)
    {
        const int na4 = 2048 * 576 / 4;
        const int nb4 = 512 * 3072 / 4;
        const int nc4 = 2048 * 2048 / 4;
        const int tot = na4 + nb4 + nc4;
        prep3<<<(tot + 255) / 256, 256>>>(wkv_a, wkvah, na4,
                                          wkv_b, wkvbh, nb4,
                                          out_proj_w, wouth, nc4);
    }
    // idx3: q = x @ (w_query*qscale)   <-- ncu capture lands here
    gemm_f16<true><<<dim3(16, 32), 256, GEMM_SMEM>>>(xh, wqh, qh, TOKS, 2048, 2048);
    // kv = x @ wkv_a
    gemm_f16<true><<<dim3(5, 32), 256, GEMM_SMEM>>>(xh, wkvah, kvh, TOKS, 576, 2048);
    // rope q_pe in place
    rope_qh<<<TOKS, 512>>>(qh);
    // rmsnorm latent
    rmsnorm_h<<<TOKS, 128>>>(kvh, kv_norm_w, kvch);
    // rope k_pe
    rope_kh<<<TOKS, 32>>>(kvh, kpeh);
    // kv_dec = kvc @ wkv_b
    gemm_f16<true><<<dim3(24, 32), 256, GEMM_SMEM>>>(kvch, wkvbh, kvdech, TOKS, 3072, 512);
    // causal flash attention
    flash_v3<<<dim3(SEQ / 128, 16, 2), 256, FLASH_SMEM>>>(qh, kvdech, kpeh, attnh);
    // out = attn @ out_proj_w
    gemm_f16<false><<<dim3(16, 32), 256, GEMM_SMEM>>>(attnh, wouth, out, TOKS, 2048, 2048);
}